// round 2
// baseline (speedup 1.0000x reference)
#include <cuda_runtime.h>
#include <cstdint>
#include <cstddef>

// Problem dims
#define BB 64
#define TT 256
#define DD 512
#define HH 1024
#define G4 4096
#define NCTA 128
#define UPC 8     // units per CTA
// SMEM strides (bank-conflict tuned)
#define US_STRIDE 1028
#define HS_STRIDE 36
#define ZS_STRIDE 40
#define AS_STRIDE 36
#define WS_STRIDE 72

#define GEMM_SMEM_FLOATS (2*128*AS_STRIDE + 2*32*WS_STRIDE)   // 13824
#define GEMM_SMEM_BYTES  (GEMM_SMEM_FLOATS*4)                 // 55296
#define LSTM_SMEM_FLOATS (32*US_STRIDE + 2*64*HS_STRIDE + 64*ZS_STRIDE + 64*8)
#define LSTM_SMEM_BYTES  (LSTM_SMEM_FLOATS*4)                 // 162304

// ---------------- scratch (device globals: allocation-free) ----------------
__device__ float    g_xz[(size_t)TT*BB*G4];     // [T][B][4H] fp32 (256 MB), reused by both layers
__device__ float    g_seq1[(size_t)BB*TT*HH];   // [B][T][H]  layer-1 output (64 MB)
__device__ float    g_h1[2*BB*HH];              // double-buffered h, layer 1
__device__ float    g_h2[2*BB*HH];              // double-buffered h, layer 2
__device__ unsigned g_bar[2];                   // monotonic barrier counters

// ---------------- helpers ----------------
__device__ __forceinline__ unsigned f2tf(float f) {
    unsigned u; asm("cvt.rna.tf32.f32 %0, %1;" : "=r"(u) : "f"(f)); return u;
}

__device__ __forceinline__ void mma_tf32(float c[4], const unsigned a[4], unsigned b0, unsigned b1) {
    asm volatile(
        "mma.sync.aligned.m16n8k8.row.col.f32.tf32.tf32.f32 "
        "{%0,%1,%2,%3}, {%4,%5,%6,%7}, {%8,%9}, {%0,%1,%2,%3};\n"
        : "+f"(c[0]), "+f"(c[1]), "+f"(c[2]), "+f"(c[3])
        : "r"(a[0]), "r"(a[1]), "r"(a[2]), "r"(a[3]), "r"(b0), "r"(b1));
}

__device__ __forceinline__ void cp16_ca(void* smem_dst, const float* gsrc) {
    unsigned d = (unsigned)__cvta_generic_to_shared(smem_dst);
    asm volatile("cp.async.ca.shared.global [%0], [%1], 16;\n" :: "r"(d), "l"(gsrc) : "memory");
}
__device__ __forceinline__ void cp16_cg(void* smem_dst, const float* gsrc) {
    unsigned d = (unsigned)__cvta_generic_to_shared(smem_dst);
    asm volatile("cp.async.cg.shared.global [%0], [%1], 16;\n" :: "r"(d), "l"(gsrc) : "memory");
}
__device__ __forceinline__ void cp_commit() { asm volatile("cp.async.commit_group;\n" ::: "memory"); }
__device__ __forceinline__ void cp_wait0() { asm volatile("cp.async.wait_group 0;\n" ::: "memory"); }
__device__ __forceinline__ void cp_wait1() { asm volatile("cp.async.wait_group 1;\n" ::: "memory"); }

__device__ __forceinline__ float sigf(float x) { return 1.f / (1.f + __expf(-x)); }

// ---------------- init: zero h buffers + barrier counters each replay ----------------
__global__ void init_zero() {
    int idx = blockIdx.x * blockDim.x + threadIdx.x;
    int stride = gridDim.x * blockDim.x;
    for (int i = idx; i < 2 * BB * HH; i += stride) { g_h1[i] = 0.f; g_h2[i] = 0.f; }
    if (idx == 0) { g_bar[0] = 0u; g_bar[1] = 0u; }
}

// ---------------- feedforward GEMM: g_xz[t*B+b][0:4096] = A(b,t) @ W + bias ----------------
// A row for output row m: A + (m%B)*sAb + (m/B)*sAt ; Abase==nullptr -> use g_seq1
__global__ void __launch_bounds__(256)
gemm_xw(const float* __restrict__ Abase, const float* __restrict__ W,
        const float* __restrict__ bias, int K, int sAb, int sAt)
{
    extern __shared__ float sm[];
    float* As = sm;                      // [2][128][AS_STRIDE]
    float* Ws = sm + 2 * 128 * AS_STRIDE; // [2][32][WS_STRIDE]
    const float* A = Abase ? Abase : g_seq1;

    const int tid = threadIdx.x;
    const int lane = tid & 31, w = tid >> 5;
    const int wm = w & 3, wn = w >> 2;
    const int bn = blockIdx.x * 64;
    const int bm = blockIdx.y * 128;

    float cf[2][4][4];
#pragma unroll
    for (int i = 0; i < 2; i++)
#pragma unroll
        for (int j = 0; j < 4; j++)
#pragma unroll
            for (int q = 0; q < 4; q++) cf[i][j][q] = 0.f;

    const int KB = K >> 5;

    // stage loader
    auto dostage = [&](int stage, int kb) {
        const int k0 = kb * 32;
#pragma unroll
        for (int i = 0; i < 4; i++) {           // A: 128 rows x 8 float4
            int idx = i * 256 + tid;
            int r = idx >> 3, s = idx & 7;
            int m = bm + r;
            const float* src = A + (size_t)(m & 63) * sAb + (size_t)(m >> 6) * sAt + k0 + s * 4;
            cp16_ca(&As[stage * 128 * AS_STRIDE + r * AS_STRIDE + s * 4], src);
        }
#pragma unroll
        for (int i = 0; i < 2; i++) {           // W: 32 rows x 16 float4
            int idx = i * 256 + tid;
            int r = idx >> 4, s = idx & 15;
            const float* src = W + (size_t)(k0 + r) * G4 + bn + s * 4;
            cp16_ca(&Ws[stage * 32 * WS_STRIDE + r * WS_STRIDE + s * 4], src);
        }
        cp_commit();
    };

    dostage(0, 0);
    const int lr = lane >> 2, lc = lane & 3;

    for (int kb = 0; kb < KB; kb++) {
        int st = kb & 1;
        if (kb + 1 < KB) { dostage(st ^ 1, kb + 1); cp_wait1(); }
        else             { cp_wait0(); }
        __syncthreads();
        const float* as = As + st * 128 * AS_STRIDE;
        const float* ws = Ws + st * 32 * WS_STRIDE;
#pragma unroll
        for (int k8 = 0; k8 < 4; k8++) {
            unsigned a[2][4];
#pragma unroll
            for (int mt = 0; mt < 2; mt++) {
                int r0 = wm * 32 + mt * 16 + lr;
                a[mt][0] = f2tf(as[r0 * AS_STRIDE + k8 * 8 + lc]);
                a[mt][1] = f2tf(as[(r0 + 8) * AS_STRIDE + k8 * 8 + lc]);
                a[mt][2] = f2tf(as[r0 * AS_STRIDE + k8 * 8 + lc + 4]);
                a[mt][3] = f2tf(as[(r0 + 8) * AS_STRIDE + k8 * 8 + lc + 4]);
            }
#pragma unroll
            for (int nt = 0; nt < 4; nt++) {
                int c0 = wn * 32 + nt * 8 + lr;
                unsigned b0 = f2tf(ws[(k8 * 8 + lc) * WS_STRIDE + c0]);
                unsigned b1 = f2tf(ws[(k8 * 8 + lc + 4) * WS_STRIDE + c0]);
#pragma unroll
                for (int mt = 0; mt < 2; mt++) mma_tf32(cf[mt][nt], a[mt], b0, b1);
            }
        }
        __syncthreads();
    }

    // epilogue (+bias)
#pragma unroll
    for (int mt = 0; mt < 2; mt++) {
#pragma unroll
        for (int nt = 0; nt < 4; nt++) {
            int gr = bm + wm * 32 + mt * 16 + lr;
            int gc = bn + wn * 32 + nt * 8 + 2 * lc;
            float bv0 = bias[gc], bv1 = bias[gc + 1];
            float2 v;
            v.x = cf[mt][nt][0] + bv0; v.y = cf[mt][nt][1] + bv1;
            *(float2*)&g_xz[(size_t)gr * G4 + gc] = v;
            v.x = cf[mt][nt][2] + bv0; v.y = cf[mt][nt][3] + bv1;
            *(float2*)&g_xz[(size_t)(gr + 8) * G4 + gc] = v;
        }
    }
}

// ---------------- persistent LSTM scan ----------------
__device__ __forceinline__ void lstm_load_h(const float* hr, int kk, float* stage, int tid) {
#pragma unroll
    for (int i = 0; i < 2; i++) {   // 64 rows x 8 float4
        int idx = i * 256 + tid;
        int r = idx >> 3, s = idx & 7;
        cp16_cg(stage + r * HS_STRIDE + s * 4, hr + (size_t)r * HH + kk * 32 + s * 4);
    }
    cp_commit();
}

__global__ void __launch_bounds__(256)
lstm_scan(const float* __restrict__ U, int layer)
{
    extern __shared__ float sm[];
    float* Us = sm;                                   // [32][US_STRIDE] tf32
    float* Hs = Us + 32 * US_STRIDE;                  // [2][64][HS_STRIDE]
    float* Zs = Hs + 2 * 64 * HS_STRIDE;              // [64][ZS_STRIDE]
    float* Cs = Zs + 64 * ZS_STRIDE;                  // [64][8] cell state (fp32)

    float* hbuf = (layer == 0) ? g_h1 : g_h2;
    float* seqo = (layer == 0) ? g_seq1 : nullptr;
    unsigned* bar = &g_bar[layer];

    const int tid = threadIdx.x, lane = tid & 31, w = tid >> 5;
    const int mw = w & 3, nw = w >> 2;
    const int u0 = blockIdx.x * UPC;

    // Load U slice: Us[c][k] = tf32(U[k][gate*1024 + u0 + u]), c = gate*8+u
    for (int idx = tid; idx < 32 * HH; idx += 256) {
        int k = idx >> 5, c = idx & 31;
        int gcol = (c >> 3) * HH + u0 + (c & 7);
        Us[c * US_STRIDE + k] = __uint_as_float(f2tf(U[(size_t)k * G4 + gcol]));
    }
    for (int i = tid; i < 64 * 8; i += 256) Cs[i] = 0.f;
    __syncthreads();

    const int lr = lane >> 2, lc = lane & 3;

    for (int t = 0; t < TT; t++) {
        const float* hr = hbuf + (t & 1) * (BB * HH);
        float* hw = hbuf + ((t + 1) & 1) * (BB * HH);

        float cf[2][4];
#pragma unroll
        for (int i = 0; i < 2; i++)
#pragma unroll
            for (int j = 0; j < 4; j++) cf[i][j] = 0.f;

        lstm_load_h(hr, 0, Hs, tid);
        int buf = 0;
        for (int kk = 0; kk < 32; kk++) {
            if (kk < 31) { lstm_load_h(hr, kk + 1, Hs + (buf ^ 1) * 64 * HS_STRIDE, tid); cp_wait1(); }
            else         { cp_wait0(); }
            __syncthreads();
            const float* hs = Hs + buf * 64 * HS_STRIDE;
#pragma unroll
            for (int k8 = 0; k8 < 4; k8++) {
                unsigned a[4];
                int r0 = mw * 16 + lr;
                a[0] = __float_as_uint(hs[r0 * HS_STRIDE + k8 * 8 + lc]);
                a[1] = __float_as_uint(hs[(r0 + 8) * HS_STRIDE + k8 * 8 + lc]);
                a[2] = __float_as_uint(hs[r0 * HS_STRIDE + k8 * 8 + lc + 4]);
                a[3] = __float_as_uint(hs[(r0 + 8) * HS_STRIDE + k8 * 8 + lc + 4]);
                int kg = kk * 32 + k8 * 8;
#pragma unroll
                for (int nt = 0; nt < 2; nt++) {
                    int c0 = nw * 16 + nt * 8 + lr;
                    unsigned b0 = __float_as_uint(Us[c0 * US_STRIDE + kg + lc]);
                    unsigned b1 = __float_as_uint(Us[c0 * US_STRIDE + kg + lc + 4]);
                    mma_tf32(cf[nt], a, b0, b1);
                }
            }
            __syncthreads();
            buf ^= 1;
        }

        // z fragments -> SMEM
#pragma unroll
        for (int nt = 0; nt < 2; nt++) {
            int zr = mw * 16 + lr;
            int zc = nw * 16 + nt * 8 + 2 * lc;
            *(float2*)&Zs[zr * ZS_STRIDE + zc]       = make_float2(cf[nt][0], cf[nt][1]);
            *(float2*)&Zs[(zr + 8) * ZS_STRIDE + zc] = make_float2(cf[nt][2], cf[nt][3]);
        }
        __syncthreads();

        // gates + state update (fp32)
        const float* xz = g_xz + (size_t)(t * BB) * G4;
        for (int p = tid; p < BB * UPC; p += 256) {
            int b = p >> 3, u = p & 7;
            const float* xzr = xz + (size_t)b * G4 + u0 + u;
            float zi = Zs[b * ZS_STRIDE + u]      + xzr[0];
            float zf = Zs[b * ZS_STRIDE + 8 + u]  + xzr[HH];
            float zg = Zs[b * ZS_STRIDE + 16 + u] + xzr[2 * HH];
            float zo = Zs[b * ZS_STRIDE + 24 + u] + xzr[3 * HH];
            float fi = sigf(zi), ff = sigf(zf), fo = sigf(zo);
            float fg = tanhf(zg);
            float cn = ff * Cs[b * 8 + u] + fi * fg;
            Cs[b * 8 + u] = cn;
            float hn = fo * tanhf(cn);
            hw[(size_t)b * HH + u0 + u] = __uint_as_float(f2tf(hn)); // pre-rounded for next mma
            if (seqo) seqo[((size_t)b * TT + t) * HH + u0 + u] = hn;
        }

        // grid barrier (monotonic counter, release/acquire via fences)
        __threadfence();
        __syncthreads();
        if (tid == 0) {
            atomicAdd(bar, 1u);
            unsigned target = (unsigned)(NCTA * (t + 1));
            while (*((volatile unsigned*)bar) < target) { }
        }
        __syncthreads();
        __threadfence();
    }
}

// ---------------- final dense: out[b][o] = h2_final[b] . Wd[:,o] + bd[o] ----------------
__global__ void __launch_bounds__(512)
dense_out(const float* __restrict__ Wd, const float* __restrict__ bd, float* __restrict__ out)
{
    __shared__ float hs[HH];
    int b = blockIdx.x;
    const float* h = g_h2; // h_256 lives in stage 0 (T even)
    for (int i = threadIdx.x; i < HH; i += 512) hs[i] = h[(size_t)b * HH + i];
    __syncthreads();
    int o = threadIdx.x;
    float acc = bd[o];
#pragma unroll 8
    for (int k = 0; k < HH; k++) acc += hs[k] * Wd[(size_t)k * 512 + o];
    out[(size_t)b * 512 + o] = acc;
}

// ---------------- launch ----------------
extern "C" void kernel_launch(void* const* d_in, const int* in_sizes, int n_in,
                              void* d_out, int out_size)
{
    (void)in_sizes; (void)n_in; (void)out_size;
    const float* x  = (const float*)d_in[0];
    const float* W1 = (const float*)d_in[1];
    const float* U1 = (const float*)d_in[2];
    const float* b1 = (const float*)d_in[3];
    const float* W2 = (const float*)d_in[4];
    const float* U2 = (const float*)d_in[5];
    const float* b2 = (const float*)d_in[6];
    const float* Wd = (const float*)d_in[7];
    const float* bd = (const float*)d_in[8];
    float* out = (float*)d_out;

    cudaFuncSetAttribute(gemm_xw,  cudaFuncAttributeMaxDynamicSharedMemorySize, GEMM_SMEM_BYTES);
    cudaFuncSetAttribute(lstm_scan, cudaFuncAttributeMaxDynamicSharedMemorySize, LSTM_SMEM_BYTES);

    init_zero<<<128, 256>>>();

    dim3 gg(G4 / 64, (BB * TT) / 128);
    // layer 1: xz = x @ W1 + b1   (A row (b,t): x + b*T*D + t*D)
    gemm_xw<<<gg, 256, GEMM_SMEM_BYTES>>>(x, W1, b1, DD, TT * DD, DD);
    lstm_scan<<<NCTA, 256, LSTM_SMEM_BYTES>>>(U1, 0);
    // layer 2: xz = seq1 @ W2 + b2 (A row (b,t): seq1 + b*T*H + t*H)
    gemm_xw<<<gg, 256, GEMM_SMEM_BYTES>>>(nullptr, W2, b2, HH, TT * HH, HH);
    lstm_scan<<<NCTA, 256, LSTM_SMEM_BYTES>>>(U2, 1);

    dense_out<<<BB, 512>>>(Wd, bd, out);
}

// round 3
// speedup vs baseline: 1.0574x; 1.0574x over previous
#include <cuda_runtime.h>
#include <cstdint>
#include <cstddef>

// Problem dims
#define BB 64
#define TT 256
#define DD 512
#define HH 1024
#define G4 4096
#define NCTA 128
#define UPC 8     // units per CTA
// SMEM strides (bank-conflict tuned)
#define US_STRIDE 1028
#define ZS_STRIDE 40
#define AS_STRIDE 36
#define WS_STRIDE 72
// LSTM h chunking
#define HCH 64          // columns per chunk
#define NCH 16          // chunks per step (HH / HCH)
#define HCH_STRIDE 68   // smem row stride for a chunk
#define HSTAGES 4

#define GEMM_STAGE_FLOATS (128*AS_STRIDE + 32*WS_STRIDE)      // 6912
#define GEMM_SMEM_FLOATS (3*GEMM_STAGE_FLOATS)                // 20736
#define GEMM_SMEM_BYTES  (GEMM_SMEM_FLOATS*4)                 // 82944
#define LSTM_SMEM_FLOATS (32*US_STRIDE + HSTAGES*64*HCH_STRIDE + 64*ZS_STRIDE + 64*8)
#define LSTM_SMEM_BYTES  (LSTM_SMEM_FLOATS*4)                 // 213504

// ---------------- scratch (device globals: allocation-free) ----------------
__device__ float    g_xz[(size_t)TT*BB*G4];     // [T][B][4H] fp32 (256 MB), reused by both layers
__device__ float    g_seq1[(size_t)BB*TT*HH];   // [B][T][H]  layer-1 output, stored tf32-rounded
__device__ float    g_xr[(size_t)BB*TT*DD];     // x pre-rounded to tf32
__device__ float    g_W1r[(size_t)DD*G4];       // W1 pre-rounded
__device__ float    g_W2r[(size_t)HH*G4];       // W2 pre-rounded
__device__ float    g_h1[2*BB*HH];              // double-buffered h, layer 1 (tf32-rounded)
__device__ float    g_h2[2*BB*HH];              // double-buffered h, layer 2 (tf32-rounded)
__device__ unsigned g_bar[2];                   // monotonic barrier counters

// ---------------- helpers ----------------
__device__ __forceinline__ unsigned f2tf(float f) {
    unsigned u; asm("cvt.rna.tf32.f32 %0, %1;" : "=r"(u) : "f"(f)); return u;
}

__device__ __forceinline__ void mma_tf32(float c[4], const unsigned a[4], unsigned b0, unsigned b1) {
    asm volatile(
        "mma.sync.aligned.m16n8k8.row.col.f32.tf32.tf32.f32 "
        "{%0,%1,%2,%3}, {%4,%5,%6,%7}, {%8,%9}, {%0,%1,%2,%3};\n"
        : "+f"(c[0]), "+f"(c[1]), "+f"(c[2]), "+f"(c[3])
        : "r"(a[0]), "r"(a[1]), "r"(a[2]), "r"(a[3]), "r"(b0), "r"(b1));
}

__device__ __forceinline__ void cp16_ca(void* smem_dst, const float* gsrc) {
    unsigned d = (unsigned)__cvta_generic_to_shared(smem_dst);
    asm volatile("cp.async.ca.shared.global [%0], [%1], 16;\n" :: "r"(d), "l"(gsrc) : "memory");
}
__device__ __forceinline__ void cp16_cg(void* smem_dst, const float* gsrc) {
    unsigned d = (unsigned)__cvta_generic_to_shared(smem_dst);
    asm volatile("cp.async.cg.shared.global [%0], [%1], 16;\n" :: "r"(d), "l"(gsrc) : "memory");
}
__device__ __forceinline__ void cp_commit() { asm volatile("cp.async.commit_group;\n" ::: "memory"); }
__device__ __forceinline__ void cp_wait1() { asm volatile("cp.async.wait_group 1;\n" ::: "memory"); }
__device__ __forceinline__ void cp_wait2() { asm volatile("cp.async.wait_group 2;\n" ::: "memory"); }

__device__ __forceinline__ float sigf(float x) { return 1.f / (1.f + __expf(-x)); }

// ---------------- init: zero h buffers + barrier counters each replay ----------------
__global__ void init_zero() {
    int idx = blockIdx.x * blockDim.x + threadIdx.x;
    int stride = gridDim.x * blockDim.x;
    for (int i = idx; i < 2 * BB * HH; i += stride) { g_h1[i] = 0.f; g_h2[i] = 0.f; }
    if (idx == 0) { g_bar[0] = 0u; g_bar[1] = 0u; }
}

// ---------------- pre-round fp32 -> tf32 bits (once per replay) ----------------
__global__ void __launch_bounds__(256)
cvt_round(const float* __restrict__ src, int which, int n4) {
    float* dst = (which == 0) ? g_xr : (which == 1) ? g_W1r : g_W2r;
    int idx = blockIdx.x * blockDim.x + threadIdx.x;
    int stride = gridDim.x * blockDim.x;
    const float4* s4 = (const float4*)src;
    float4* d4 = (float4*)dst;
    for (int i = idx; i < n4; i += stride) {
        float4 v = s4[i];
        v.x = __uint_as_float(f2tf(v.x));
        v.y = __uint_as_float(f2tf(v.y));
        v.z = __uint_as_float(f2tf(v.z));
        v.w = __uint_as_float(f2tf(v.w));
        d4[i] = v;
    }
}

// ---------------- feedforward GEMM: g_xz[t*B+b][0:4096] = A(b,t) @ W + bias ----------------
// asel 0: A = g_xr (layout [B][T][D]); asel 1: A = g_seq1 ([B][T][H]). Inputs pre-rounded to tf32.
__global__ void __launch_bounds__(256)
gemm_xw(int asel, const float* __restrict__ bias, int K, int sAb, int sAt)
{
    extern __shared__ float sm[];
    const float* A = asel ? g_seq1 : g_xr;
    const float* W = asel ? g_W2r : g_W1r;

    const int tid = threadIdx.x;
    const int lane = tid & 31, w = tid >> 5;
    const int wm = w & 3, wn = w >> 2;
    const int bn = blockIdx.x * 64;
    const int bm = blockIdx.y * 128;

    float cf[2][4][4];
#pragma unroll
    for (int i = 0; i < 2; i++)
#pragma unroll
        for (int j = 0; j < 4; j++)
#pragma unroll
            for (int q = 0; q < 4; q++) cf[i][j][q] = 0.f;

    const int KB = K >> 5;

    auto dostage = [&](int slot, int kb) {
        float* As = sm + slot * GEMM_STAGE_FLOATS;
        float* Ws = As + 128 * AS_STRIDE;
        const int k0 = kb * 32;
#pragma unroll
        for (int i = 0; i < 4; i++) {           // A: 128 rows x 8 float4
            int idx = i * 256 + tid;
            int r = idx >> 3, s = idx & 7;
            int m = bm + r;
            const float* src = A + (size_t)(m & 63) * sAb + (size_t)(m >> 6) * sAt + k0 + s * 4;
            cp16_ca(&As[r * AS_STRIDE + s * 4], src);
        }
#pragma unroll
        for (int i = 0; i < 2; i++) {           // W: 32 rows x 16 float4
            int idx = i * 256 + tid;
            int r = idx >> 4, s = idx & 15;
            const float* src = W + (size_t)(k0 + r) * G4 + bn + s * 4;
            cp16_ca(&Ws[r * WS_STRIDE + s * 4], src);
        }
    };

    // 3-stage ring, always-commit: 1 sync per kb
    dostage(0, 0); cp_commit();
    dostage(1, 1); cp_commit();

    const int lr = lane >> 2, lc = lane & 3;

    for (int kb = 0; kb < KB; kb++) {
        cp_wait1();            // chunk kb resident (<=1 newer group pending)
        __syncthreads();       // all warps done with slot (kb-1)%3
        if (kb + 2 < KB) dostage((kb + 2) % 3, kb + 2);
        cp_commit();           // empty-group commit keeps the count uniform
        const float* as = sm + (kb % 3) * GEMM_STAGE_FLOATS;
        const float* ws = as + 128 * AS_STRIDE;
#pragma unroll
        for (int k8 = 0; k8 < 4; k8++) {
            unsigned a[2][4];
#pragma unroll
            for (int mt = 0; mt < 2; mt++) {
                int r0 = wm * 32 + mt * 16 + lr;
                a[mt][0] = __float_as_uint(as[r0 * AS_STRIDE + k8 * 8 + lc]);
                a[mt][1] = __float_as_uint(as[(r0 + 8) * AS_STRIDE + k8 * 8 + lc]);
                a[mt][2] = __float_as_uint(as[r0 * AS_STRIDE + k8 * 8 + lc + 4]);
                a[mt][3] = __float_as_uint(as[(r0 + 8) * AS_STRIDE + k8 * 8 + lc + 4]);
            }
#pragma unroll
            for (int nt = 0; nt < 4; nt++) {
                int c0 = wn * 32 + nt * 8 + lr;
                unsigned b0 = __float_as_uint(ws[(k8 * 8 + lc) * WS_STRIDE + c0]);
                unsigned b1 = __float_as_uint(ws[(k8 * 8 + lc + 4) * WS_STRIDE + c0]);
#pragma unroll
                for (int mt = 0; mt < 2; mt++) mma_tf32(cf[mt][nt], a[mt], b0, b1);
            }
        }
    }

    // epilogue (+bias)
#pragma unroll
    for (int mt = 0; mt < 2; mt++) {
#pragma unroll
        for (int nt = 0; nt < 4; nt++) {
            int gr = bm + wm * 32 + mt * 16 + lr;
            int gc = bn + wn * 32 + nt * 8 + 2 * lc;
            float bv0 = bias[gc], bv1 = bias[gc + 1];
            float2 v;
            v.x = cf[mt][nt][0] + bv0; v.y = cf[mt][nt][1] + bv1;
            *(float2*)&g_xz[(size_t)gr * G4 + gc] = v;
            v.x = cf[mt][nt][2] + bv0; v.y = cf[mt][nt][3] + bv1;
            *(float2*)&g_xz[(size_t)(gr + 8) * G4 + gc] = v;
        }
    }
}

// ---------------- persistent LSTM scan ----------------
__device__ __forceinline__ void lstm_load_chunk(const float* hr, int ch, float* stage, int tid) {
#pragma unroll
    for (int i = 0; i < 4; i++) {   // 64 rows x 16 float4
        int idx = i * 256 + tid;
        int r = idx >> 4, s = idx & 15;
        cp16_cg(stage + r * HCH_STRIDE + s * 4, hr + (size_t)r * HH + ch * HCH + s * 4);
    }
}

__global__ void __launch_bounds__(256)
lstm_scan(const float* __restrict__ U, int layer)
{
    extern __shared__ float sm[];
    float* Us  = sm;                                        // [32][US_STRIDE] tf32
    float* Hst = Us + 32 * US_STRIDE;                       // [4][64][HCH_STRIDE]
    float* Zs  = Hst + HSTAGES * 64 * HCH_STRIDE;           // [64][ZS_STRIDE]
    float* Cs  = Zs + 64 * ZS_STRIDE;                       // [64][8] cell state (fp32)

    float* hbuf = (layer == 0) ? g_h1 : g_h2;
    float* seqo = (layer == 0) ? g_seq1 : nullptr;
    unsigned* bar = &g_bar[layer];

    const int tid = threadIdx.x, lane = tid & 31, w = tid >> 5;
    const int mw = w & 3, nw = w >> 2;
    const int u0 = blockIdx.x * UPC;

    // Load U slice: Us[c][k] = tf32(U[k][gate*1024 + u0 + u]), c = gate*8+u
    for (int idx = tid; idx < 32 * HH; idx += 256) {
        int k = idx >> 5, c = idx & 31;
        int gcol = (c >> 3) * HH + u0 + (c & 7);
        Us[c * US_STRIDE + k] = __uint_as_float(f2tf(U[(size_t)k * G4 + gcol]));
    }
    for (int i = tid; i < 64 * 8; i += 256) Cs[i] = 0.f;
    __syncthreads();

    const int lr = lane >> 2, lc = lane & 3;

    for (int t = 0; t < TT; t++) {
        const float* hr = hbuf + (t & 1) * (BB * HH);
        float* hw = hbuf + ((t + 1) & 1) * (BB * HH);

        float cf[2][4];
#pragma unroll
        for (int i = 0; i < 2; i++)
#pragma unroll
            for (int j = 0; j < 4; j++) cf[i][j] = 0.f;

        // 4-stage ring over 16 chunks, 1 sync per chunk
        lstm_load_chunk(hr, 0, Hst + 0 * 64 * HCH_STRIDE, tid); cp_commit();
        lstm_load_chunk(hr, 1, Hst + 1 * 64 * HCH_STRIDE, tid); cp_commit();
        lstm_load_chunk(hr, 2, Hst + 2 * 64 * HCH_STRIDE, tid); cp_commit();

        for (int ch = 0; ch < NCH; ch++) {
            cp_wait2();            // chunk ch resident
            __syncthreads();       // everyone finished slot (ch-1)&3
            if (ch + 3 < NCH) lstm_load_chunk(hr, ch + 3, Hst + ((ch + 3) & 3) * 64 * HCH_STRIDE, tid);
            cp_commit();
            const float* hs = Hst + (ch & 3) * 64 * HCH_STRIDE;
#pragma unroll
            for (int k8 = 0; k8 < 8; k8++) {
                unsigned a[4];
                int r0 = mw * 16 + lr;
                a[0] = __float_as_uint(hs[r0 * HCH_STRIDE + k8 * 8 + lc]);
                a[1] = __float_as_uint(hs[(r0 + 8) * HCH_STRIDE + k8 * 8 + lc]);
                a[2] = __float_as_uint(hs[r0 * HCH_STRIDE + k8 * 8 + lc + 4]);
                a[3] = __float_as_uint(hs[(r0 + 8) * HCH_STRIDE + k8 * 8 + lc + 4]);
                int kg = ch * HCH + k8 * 8;
#pragma unroll
                for (int nt = 0; nt < 2; nt++) {
                    int c0 = nw * 16 + nt * 8 + lr;
                    unsigned b0 = __float_as_uint(Us[c0 * US_STRIDE + kg + lc]);
                    unsigned b1 = __float_as_uint(Us[c0 * US_STRIDE + kg + lc + 4]);
                    mma_tf32(cf[nt], a, b0, b1);
                }
            }
        }

        // z fragments -> SMEM
#pragma unroll
        for (int nt = 0; nt < 2; nt++) {
            int zr = mw * 16 + lr;
            int zc = nw * 16 + nt * 8 + 2 * lc;
            *(float2*)&Zs[zr * ZS_STRIDE + zc]       = make_float2(cf[nt][0], cf[nt][1]);
            *(float2*)&Zs[(zr + 8) * ZS_STRIDE + zc] = make_float2(cf[nt][2], cf[nt][3]);
        }
        __syncthreads();

        // gates + state update (fp32)
        const float* xz = g_xz + (size_t)(t * BB) * G4;
        for (int p = tid; p < BB * UPC; p += 256) {
            int b = p >> 3, u = p & 7;
            const float* xzr = xz + (size_t)b * G4 + u0 + u;
            float zi = Zs[b * ZS_STRIDE + u]      + xzr[0];
            float zf = Zs[b * ZS_STRIDE + 8 + u]  + xzr[HH];
            float zg = Zs[b * ZS_STRIDE + 16 + u] + xzr[2 * HH];
            float zo = Zs[b * ZS_STRIDE + 24 + u] + xzr[3 * HH];
            float fi = sigf(zi), ff = sigf(zf), fo = sigf(zo);
            float fg = tanhf(zg);
            float cn = ff * Cs[b * 8 + u] + fi * fg;
            Cs[b * 8 + u] = cn;
            float hn = fo * tanhf(cn);
            float hnr = __uint_as_float(f2tf(hn));
            hw[(size_t)b * HH + u0 + u] = hnr;                        // pre-rounded for next mma
            if (seqo) seqo[((size_t)b * TT + t) * HH + u0 + u] = hnr; // pre-rounded for layer-2 gemm
        }

        // grid barrier (monotonic counter, release/acquire via fences)
        __threadfence();
        __syncthreads();
        if (tid == 0) {
            atomicAdd(bar, 1u);
            unsigned target = (unsigned)(NCTA * (t + 1));
            while (*((volatile unsigned*)bar) < target) { }
        }
        __syncthreads();
        __threadfence();
    }
}

// ---------------- final dense: out[b][o] = h2_final[b] . Wd[:,o] + bd[o] ----------------
__global__ void __launch_bounds__(512)
dense_out(const float* __restrict__ Wd, const float* __restrict__ bd, float* __restrict__ out)
{
    __shared__ float hs[HH];
    int b = blockIdx.x;
    const float* h = g_h2; // h_256 lives in stage 0 (T even)
    for (int i = threadIdx.x; i < HH; i += 512) hs[i] = h[(size_t)b * HH + i];
    __syncthreads();
    int o = threadIdx.x;
    float acc = bd[o];
#pragma unroll 8
    for (int k = 0; k < HH; k++) acc += hs[k] * Wd[(size_t)k * 512 + o];
    out[(size_t)b * 512 + o] = acc;
}

// ---------------- launch ----------------
extern "C" void kernel_launch(void* const* d_in, const int* in_sizes, int n_in,
                              void* d_out, int out_size)
{
    (void)in_sizes; (void)n_in; (void)out_size;
    const float* x  = (const float*)d_in[0];
    const float* W1 = (const float*)d_in[1];
    const float* U1 = (const float*)d_in[2];
    const float* b1 = (const float*)d_in[3];
    const float* W2 = (const float*)d_in[4];
    const float* U2 = (const float*)d_in[5];
    const float* b2 = (const float*)d_in[6];
    const float* Wd = (const float*)d_in[7];
    const float* bd = (const float*)d_in[8];
    float* out = (float*)d_out;

    cudaFuncSetAttribute(gemm_xw,  cudaFuncAttributeMaxDynamicSharedMemorySize, GEMM_SMEM_BYTES);
    cudaFuncSetAttribute(lstm_scan, cudaFuncAttributeMaxDynamicSharedMemorySize, LSTM_SMEM_BYTES);

    init_zero<<<128, 256>>>();
    cvt_round<<<1024, 256>>>(x,  0, (BB * TT * DD) / 4);
    cvt_round<<<1024, 256>>>(W1, 1, (DD * G4) / 4);
    cvt_round<<<1024, 256>>>(W2, 2, (HH * G4) / 4);

    dim3 gg(G4 / 64, (BB * TT) / 128);
    // layer 1: xz = x @ W1 + b1   (A row (b,t): x + b*T*D + t*D)
    gemm_xw<<<gg, 256, GEMM_SMEM_BYTES>>>(0, b1, DD, TT * DD, DD);
    lstm_scan<<<NCTA, 256, LSTM_SMEM_BYTES>>>(U1, 0);
    // layer 2: xz = seq1 @ W2 + b2 (A row (b,t): seq1 + b*T*H + t*H)
    gemm_xw<<<gg, 256, GEMM_SMEM_BYTES>>>(1, b2, HH, TT * HH, HH);
    lstm_scan<<<NCTA, 256, LSTM_SMEM_BYTES>>>(U2, 1);

    dense_out<<<BB, 512>>>(Wd, bd, out);
}

// round 4
// speedup vs baseline: 1.0818x; 1.0231x over previous
#include <cuda_runtime.h>
#include <cstdint>
#include <cstddef>

// Problem dims
#define BB 64
#define TT 256
#define DD 512
#define HH 1024
#define G4 4096
#define NCTA 128
#define UPC 8     // units per CTA
// SMEM strides (bank-conflict tuned)
#define US_STRIDE 1028
#define ZS_STRIDE 40
#define AS_STRIDE 36
#define WS_STRIDE 72
// LSTM h chunking
#define HCH 64          // columns per chunk
#define NCH 16          // chunks per step (HH / HCH)
#define HCH_STRIDE 68   // smem row stride for a chunk
#define HSTAGES 4

#define GEMM_STAGE_FLOATS (128*AS_STRIDE + 32*WS_STRIDE)      // 6912
#define GEMM_SMEM_FLOATS (3*GEMM_STAGE_FLOATS)                // 20736
#define GEMM_SMEM_BYTES  (GEMM_SMEM_FLOATS*4)                 // 82944
#define LSTM_SMEM_FLOATS (32*US_STRIDE + HSTAGES*64*HCH_STRIDE + 64*ZS_STRIDE + 64*8)
#define LSTM_SMEM_BYTES  (LSTM_SMEM_FLOATS*4)                 // 213504

// ---------------- scratch (device globals: allocation-free) ----------------
__device__ float    g_xz[(size_t)TT*BB*G4];     // [T][B][4H] fp32 (256 MB), reused by both layers
__device__ float    g_seq1[(size_t)BB*TT*HH];   // [B][T][H]  layer-1 output, stored tf32-rounded
__device__ float    g_xr[(size_t)BB*TT*DD];     // x pre-rounded to tf32
__device__ float    g_W1r[(size_t)DD*G4];       // W1 pre-rounded
__device__ float    g_W2r[(size_t)HH*G4];       // W2 pre-rounded
__device__ float    g_h1[2*BB*HH];              // double-buffered h, layer 1 (tf32-rounded)
__device__ float    g_h2[2*BB*HH];              // double-buffered h, layer 2 (tf32-rounded)
// barrier state: per-CTA arrive slots (128B stride = private L2 lines) + one release epoch per layer
__device__ unsigned g_flag[2][NCTA * 32];
__device__ unsigned g_epoch[2];

// ---------------- helpers ----------------
__device__ __forceinline__ unsigned f2tf(float f) {
    unsigned u; asm("cvt.rna.tf32.f32 %0, %1;" : "=r"(u) : "f"(f)); return u;
}

__device__ __forceinline__ void mma_tf32(float c[4], const unsigned a[4], unsigned b0, unsigned b1) {
    asm volatile(
        "mma.sync.aligned.m16n8k8.row.col.f32.tf32.tf32.f32 "
        "{%0,%1,%2,%3}, {%4,%5,%6,%7}, {%8,%9}, {%0,%1,%2,%3};\n"
        : "+f"(c[0]), "+f"(c[1]), "+f"(c[2]), "+f"(c[3])
        : "r"(a[0]), "r"(a[1]), "r"(a[2]), "r"(a[3]), "r"(b0), "r"(b1));
}

__device__ __forceinline__ void cp16_ca(void* smem_dst, const float* gsrc) {
    unsigned d = (unsigned)__cvta_generic_to_shared(smem_dst);
    asm volatile("cp.async.ca.shared.global [%0], [%1], 16;\n" :: "r"(d), "l"(gsrc) : "memory");
}
__device__ __forceinline__ void cp16_cg(void* smem_dst, const float* gsrc) {
    unsigned d = (unsigned)__cvta_generic_to_shared(smem_dst);
    asm volatile("cp.async.cg.shared.global [%0], [%1], 16;\n" :: "r"(d), "l"(gsrc) : "memory");
}
__device__ __forceinline__ void cp_commit() { asm volatile("cp.async.commit_group;\n" ::: "memory"); }
__device__ __forceinline__ void cp_wait1() { asm volatile("cp.async.wait_group 1;\n" ::: "memory"); }
__device__ __forceinline__ void cp_wait2() { asm volatile("cp.async.wait_group 2;\n" ::: "memory"); }

__device__ __forceinline__ float sigf(float x) { return 1.f / (1.f + __expf(-x)); }

// ---------------- init: zero h buffers + barrier state each replay ----------------
__global__ void init_zero() {
    int idx = blockIdx.x * blockDim.x + threadIdx.x;
    int stride = gridDim.x * blockDim.x;
    for (int i = idx; i < 2 * BB * HH; i += stride) { g_h1[i] = 0.f; g_h2[i] = 0.f; }
    for (int i = idx; i < NCTA * 32; i += stride) { g_flag[0][i] = 0u; g_flag[1][i] = 0u; }
    if (idx == 0) { g_epoch[0] = 0u; g_epoch[1] = 0u; }
}

// ---------------- pre-round fp32 -> tf32 bits (once per replay) ----------------
__global__ void __launch_bounds__(256)
cvt_round(const float* __restrict__ src, int which, int n4) {
    float* dst = (which == 0) ? g_xr : (which == 1) ? g_W1r : g_W2r;
    int idx = blockIdx.x * blockDim.x + threadIdx.x;
    int stride = gridDim.x * blockDim.x;
    const float4* s4 = (const float4*)src;
    float4* d4 = (float4*)dst;
    for (int i = idx; i < n4; i += stride) {
        float4 v = s4[i];
        v.x = __uint_as_float(f2tf(v.x));
        v.y = __uint_as_float(f2tf(v.y));
        v.z = __uint_as_float(f2tf(v.z));
        v.w = __uint_as_float(f2tf(v.w));
        d4[i] = v;
    }
}

// ---------------- feedforward GEMM: g_xz[t*B+b][0:4096] = A(b,t) @ W + bias ----------------
// asel 0: A = g_xr (layout [B][T][D]); asel 1: A = g_seq1 ([B][T][H]). Inputs pre-rounded to tf32.
__global__ void __launch_bounds__(256)
gemm_xw(int asel, const float* __restrict__ bias, int K, int sAb, int sAt)
{
    extern __shared__ float sm[];
    const float* A = asel ? g_seq1 : g_xr;
    const float* W = asel ? g_W2r : g_W1r;

    const int tid = threadIdx.x;
    const int lane = tid & 31, w = tid >> 5;
    const int wm = w & 3, wn = w >> 2;
    const int bn = blockIdx.x * 64;
    const int bm = blockIdx.y * 128;

    float cf[2][4][4];
#pragma unroll
    for (int i = 0; i < 2; i++)
#pragma unroll
        for (int j = 0; j < 4; j++)
#pragma unroll
            for (int q = 0; q < 4; q++) cf[i][j][q] = 0.f;

    const int KB = K >> 5;

    auto dostage = [&](int slot, int kb) {
        float* As = sm + slot * GEMM_STAGE_FLOATS;
        float* Ws = As + 128 * AS_STRIDE;
        const int k0 = kb * 32;
#pragma unroll
        for (int i = 0; i < 4; i++) {           // A: 128 rows x 8 float4
            int idx = i * 256 + tid;
            int r = idx >> 3, s = idx & 7;
            int m = bm + r;
            const float* src = A + (size_t)(m & 63) * sAb + (size_t)(m >> 6) * sAt + k0 + s * 4;
            cp16_ca(&As[r * AS_STRIDE + s * 4], src);
        }
#pragma unroll
        for (int i = 0; i < 2; i++) {           // W: 32 rows x 16 float4
            int idx = i * 256 + tid;
            int r = idx >> 4, s = idx & 15;
            const float* src = W + (size_t)(k0 + r) * G4 + bn + s * 4;
            cp16_ca(&Ws[r * WS_STRIDE + s * 4], src);
        }
    };

    // 3-stage ring, always-commit: 1 sync per kb
    dostage(0, 0); cp_commit();
    dostage(1, 1); cp_commit();

    const int lr = lane >> 2, lc = lane & 3;

    for (int kb = 0; kb < KB; kb++) {
        cp_wait1();            // chunk kb resident (<=1 newer group pending)
        __syncthreads();       // all warps done with slot (kb-1)%3
        if (kb + 2 < KB) dostage((kb + 2) % 3, kb + 2);
        cp_commit();           // empty-group commit keeps the count uniform
        const float* as = sm + (kb % 3) * GEMM_STAGE_FLOATS;
        const float* ws = as + 128 * AS_STRIDE;
#pragma unroll
        for (int k8 = 0; k8 < 4; k8++) {
            unsigned a[2][4];
#pragma unroll
            for (int mt = 0; mt < 2; mt++) {
                int r0 = wm * 32 + mt * 16 + lr;
                a[mt][0] = __float_as_uint(as[r0 * AS_STRIDE + k8 * 8 + lc]);
                a[mt][1] = __float_as_uint(as[(r0 + 8) * AS_STRIDE + k8 * 8 + lc]);
                a[mt][2] = __float_as_uint(as[r0 * AS_STRIDE + k8 * 8 + lc + 4]);
                a[mt][3] = __float_as_uint(as[(r0 + 8) * AS_STRIDE + k8 * 8 + lc + 4]);
            }
#pragma unroll
            for (int nt = 0; nt < 4; nt++) {
                int c0 = wn * 32 + nt * 8 + lr;
                unsigned b0 = __float_as_uint(ws[(k8 * 8 + lc) * WS_STRIDE + c0]);
                unsigned b1 = __float_as_uint(ws[(k8 * 8 + lc + 4) * WS_STRIDE + c0]);
#pragma unroll
                for (int mt = 0; mt < 2; mt++) mma_tf32(cf[mt][nt], a[mt], b0, b1);
            }
        }
    }

    // epilogue (+bias)
#pragma unroll
    for (int mt = 0; mt < 2; mt++) {
#pragma unroll
        for (int nt = 0; nt < 4; nt++) {
            int gr = bm + wm * 32 + mt * 16 + lr;
            int gc = bn + wn * 32 + nt * 8 + 2 * lc;
            float bv0 = bias[gc], bv1 = bias[gc + 1];
            float2 v;
            v.x = cf[mt][nt][0] + bv0; v.y = cf[mt][nt][1] + bv1;
            *(float2*)&g_xz[(size_t)gr * G4 + gc] = v;
            v.x = cf[mt][nt][2] + bv0; v.y = cf[mt][nt][3] + bv1;
            *(float2*)&g_xz[(size_t)(gr + 8) * G4 + gc] = v;
        }
    }
}

// ---------------- persistent LSTM scan ----------------
__device__ __forceinline__ void lstm_load_chunk(const float* hr, int ch, float* stage, int tid) {
#pragma unroll
    for (int i = 0; i < 4; i++) {   // 64 rows x 16 float4
        int idx = i * 256 + tid;
        int r = idx >> 4, s = idx & 15;
        cp16_cg(stage + r * HCH_STRIDE + s * 4, hr + (size_t)r * HH + ch * HCH + s * 4);
    }
}

__global__ void __launch_bounds__(256)
lstm_scan(const float* __restrict__ U, int layer)
{
    extern __shared__ float sm[];
    float* Us  = sm;                                        // [32][US_STRIDE] tf32
    float* Hst = Us + 32 * US_STRIDE;                       // [4][64][HCH_STRIDE]
    float* Zs  = Hst + HSTAGES * 64 * HCH_STRIDE;           // [64][ZS_STRIDE]
    float* Cs  = Zs + 64 * ZS_STRIDE;                       // [64][8] cell state (fp32)

    float* hbuf = (layer == 0) ? g_h1 : g_h2;
    float* seqo = (layer == 0) ? g_seq1 : nullptr;
    volatile unsigned* flags = g_flag[layer];
    volatile unsigned* epoch = &g_epoch[layer];

    const int tid = threadIdx.x, lane = tid & 31, w = tid >> 5;
    const int mw = w & 3, nw = w >> 2;
    const int u0 = blockIdx.x * UPC;

    // Load U slice: Us[c][k] = tf32(U[k][gate*1024 + u0 + u]), c = gate*8+u
    for (int idx = tid; idx < 32 * HH; idx += 256) {
        int k = idx >> 5, c = idx & 31;
        int gcol = (c >> 3) * HH + u0 + (c & 7);
        Us[c * US_STRIDE + k] = __uint_as_float(f2tf(U[(size_t)k * G4 + gcol]));
    }
    for (int i = tid; i < 64 * 8; i += 256) Cs[i] = 0.f;
    __syncthreads();

    const int lr = lane >> 2, lc = lane & 3;

    // gate-work item ownership: p0 = tid, p1 = tid + 256 (512 items = 64 b x 8 u)
    const int b0_ = tid >> 3,        u0_ = tid & 7;
    const int b1_ = (tid + 256) >> 3, u1_ = (tid + 256) & 7;

    for (int t = 0; t < TT; t++) {
        const float* hr = hbuf + (t & 1) * (BB * HH);
        float* hw = hbuf + ((t + 1) & 1) * (BB * HH);

        // ---- prefetch this step's xz gate rows (independent of h; hidden under mma loop)
        const float* xz = g_xz + (size_t)(t * BB) * G4;
        const float* xp0 = xz + (size_t)b0_ * G4 + u0 + u0_;
        const float* xp1 = xz + (size_t)b1_ * G4 + u0 + u1_;
        float xi0 = __ldg(xp0);            float xi1 = __ldg(xp1);
        float xf0 = __ldg(xp0 + HH);       float xf1 = __ldg(xp1 + HH);
        float xg0 = __ldg(xp0 + 2 * HH);   float xg1 = __ldg(xp1 + 2 * HH);
        float xo0 = __ldg(xp0 + 3 * HH);   float xo1 = __ldg(xp1 + 3 * HH);

        float cf[2][4];
#pragma unroll
        for (int i = 0; i < 2; i++)
#pragma unroll
            for (int j = 0; j < 4; j++) cf[i][j] = 0.f;

        // 4-stage ring over 16 chunks, 1 sync per chunk
        lstm_load_chunk(hr, 0, Hst + 0 * 64 * HCH_STRIDE, tid); cp_commit();
        lstm_load_chunk(hr, 1, Hst + 1 * 64 * HCH_STRIDE, tid); cp_commit();
        lstm_load_chunk(hr, 2, Hst + 2 * 64 * HCH_STRIDE, tid); cp_commit();

        for (int ch = 0; ch < NCH; ch++) {
            cp_wait2();            // chunk ch resident
            __syncthreads();       // everyone finished slot (ch-1)&3
            if (ch + 3 < NCH) lstm_load_chunk(hr, ch + 3, Hst + ((ch + 3) & 3) * 64 * HCH_STRIDE, tid);
            cp_commit();
            const float* hs = Hst + (ch & 3) * 64 * HCH_STRIDE;
#pragma unroll
            for (int k8 = 0; k8 < 8; k8++) {
                unsigned a[4];
                int r0 = mw * 16 + lr;
                a[0] = __float_as_uint(hs[r0 * HCH_STRIDE + k8 * 8 + lc]);
                a[1] = __float_as_uint(hs[(r0 + 8) * HCH_STRIDE + k8 * 8 + lc]);
                a[2] = __float_as_uint(hs[r0 * HCH_STRIDE + k8 * 8 + lc + 4]);
                a[3] = __float_as_uint(hs[(r0 + 8) * HCH_STRIDE + k8 * 8 + lc + 4]);
                int kg = ch * HCH + k8 * 8;
#pragma unroll
                for (int nt = 0; nt < 2; nt++) {
                    int c0 = nw * 16 + nt * 8 + lr;
                    unsigned b0 = __float_as_uint(Us[c0 * US_STRIDE + kg + lc]);
                    unsigned b1 = __float_as_uint(Us[c0 * US_STRIDE + kg + lc + 4]);
                    mma_tf32(cf[nt], a, b0, b1);
                }
            }
        }

        // z fragments -> SMEM
#pragma unroll
        for (int nt = 0; nt < 2; nt++) {
            int zr = mw * 16 + lr;
            int zc = nw * 16 + nt * 8 + 2 * lc;
            *(float2*)&Zs[zr * ZS_STRIDE + zc]       = make_float2(cf[nt][0], cf[nt][1]);
            *(float2*)&Zs[(zr + 8) * ZS_STRIDE + zc] = make_float2(cf[nt][2], cf[nt][3]);
        }
        __syncthreads();

        // gates + state update (fp32); xz already in registers
        {
            // item 0
            float zi = Zs[b0_ * ZS_STRIDE + u0_]      + xi0;
            float zf = Zs[b0_ * ZS_STRIDE + 8 + u0_]  + xf0;
            float zg = Zs[b0_ * ZS_STRIDE + 16 + u0_] + xg0;
            float zo = Zs[b0_ * ZS_STRIDE + 24 + u0_] + xo0;
            float fi = sigf(zi), ff = sigf(zf), fo = sigf(zo);
            float fg = tanhf(zg);
            float cn = ff * Cs[b0_ * 8 + u0_] + fi * fg;
            Cs[b0_ * 8 + u0_] = cn;
            float hn = fo * tanhf(cn);
            float hnr = __uint_as_float(f2tf(hn));
            hw[(size_t)b0_ * HH + u0 + u0_] = hnr;
            if (seqo) seqo[((size_t)b0_ * TT + t) * HH + u0 + u0_] = hnr;
            // item 1
            zi = Zs[b1_ * ZS_STRIDE + u1_]      + xi1;
            zf = Zs[b1_ * ZS_STRIDE + 8 + u1_]  + xf1;
            zg = Zs[b1_ * ZS_STRIDE + 16 + u1_] + xg1;
            zo = Zs[b1_ * ZS_STRIDE + 24 + u1_] + xo1;
            fi = sigf(zi); ff = sigf(zf); fo = sigf(zo);
            fg = tanhf(zg);
            cn = ff * Cs[b1_ * 8 + u1_] + fi * fg;
            Cs[b1_ * 8 + u1_] = cn;
            hn = fo * tanhf(cn);
            hnr = __uint_as_float(f2tf(hn));
            hw[(size_t)b1_ * HH + u0 + u1_] = hnr;
            if (seqo) seqo[((size_t)b1_ * TT + t) * HH + u0 + u1_] = hnr;
        }

        // ---- grid barrier: per-CTA arrive slots + single release epoch ----
        __threadfence();                 // h writes visible GPU-wide
        __syncthreads();                 // whole CTA done writing h
        if (tid == 0) flags[blockIdx.x * 32] = (unsigned)(t + 1);   // private line, no serialization
        if (blockIdx.x == 0) {
            if (tid < NCTA) {            // 128 threads poll 128 distinct lines in parallel
                while (flags[tid * 32] < (unsigned)(t + 1)) { }
            }
            __syncthreads();
            if (tid == 0) *epoch = (unsigned)(t + 1);
        }
        if (tid == 0) {
            while (*epoch < (unsigned)(t + 1)) { __nanosleep(32); }
        }
        __syncthreads();
        __threadfence();
    }
}

// ---------------- final dense: out[b][o] = h2_final[b] . Wd[:,o] + bd[o] ----------------
__global__ void __launch_bounds__(512)
dense_out(const float* __restrict__ Wd, const float* __restrict__ bd, float* __restrict__ out)
{
    __shared__ float hs[HH];
    int b = blockIdx.x;
    const float* h = g_h2; // h_256 lives in stage 0 (T even)
    for (int i = threadIdx.x; i < HH; i += 512) hs[i] = h[(size_t)b * HH + i];
    __syncthreads();
    int o = threadIdx.x;
    float acc = bd[o];
#pragma unroll 8
    for (int k = 0; k < HH; k++) acc += hs[k] * Wd[(size_t)k * 512 + o];
    out[(size_t)b * 512 + o] = acc;
}

// ---------------- launch ----------------
extern "C" void kernel_launch(void* const* d_in, const int* in_sizes, int n_in,
                              void* d_out, int out_size)
{
    (void)in_sizes; (void)n_in; (void)out_size;
    const float* x  = (const float*)d_in[0];
    const float* W1 = (const float*)d_in[1];
    const float* U1 = (const float*)d_in[2];
    const float* b1 = (const float*)d_in[3];
    const float* W2 = (const float*)d_in[4];
    const float* U2 = (const float*)d_in[5];
    const float* b2 = (const float*)d_in[6];
    const float* Wd = (const float*)d_in[7];
    const float* bd = (const float*)d_in[8];
    float* out = (float*)d_out;

    cudaFuncSetAttribute(gemm_xw,  cudaFuncAttributeMaxDynamicSharedMemorySize, GEMM_SMEM_BYTES);
    cudaFuncSetAttribute(lstm_scan, cudaFuncAttributeMaxDynamicSharedMemorySize, LSTM_SMEM_BYTES);

    init_zero<<<128, 256>>>();
    cvt_round<<<1024, 256>>>(x,  0, (BB * TT * DD) / 4);
    cvt_round<<<1024, 256>>>(W1, 1, (DD * G4) / 4);
    cvt_round<<<1024, 256>>>(W2, 2, (HH * G4) / 4);

    dim3 gg(G4 / 64, (BB * TT) / 128);
    // layer 1: xz = x @ W1 + b1   (A row (b,t): x + b*T*D + t*D)
    gemm_xw<<<gg, 256, GEMM_SMEM_BYTES>>>(0, b1, DD, TT * DD, DD);
    lstm_scan<<<NCTA, 256, LSTM_SMEM_BYTES>>>(U1, 0);
    // layer 2: xz = seq1 @ W2 + b2 (A row (b,t): seq1 + b*T*H + t*H)
    gemm_xw<<<gg, 256, GEMM_SMEM_BYTES>>>(1, b2, HH, TT * HH, HH);
    lstm_scan<<<NCTA, 256, LSTM_SMEM_BYTES>>>(U2, 1);

    dense_out<<<BB, 512>>>(Wd, bd, out);
}

// round 5
// speedup vs baseline: 1.0997x; 1.0166x over previous
#include <cuda_runtime.h>
#include <cstdint>
#include <cstddef>

// Problem dims
#define BB 64
#define TT 256
#define DD 512
#define HH 1024
#define G4 4096
#define NCTA 128
#define UPC 8     // units per CTA
// SMEM strides (bank-conflict tuned)
#define US_STRIDE 1028
#define ZS_STRIDE 40
#define AS_STRIDE 36
#define WS_STRIDE 72
// LSTM h chunking
#define HCH 64          // columns per chunk
#define NCH 16          // chunks per step (HH / HCH)
#define HCH_STRIDE 68   // smem row stride for a chunk
#define HSTAGES 4

#define GEMM_STAGE_FLOATS (128*AS_STRIDE + 32*WS_STRIDE)      // 6912
#define GEMM_SMEM_FLOATS (3*GEMM_STAGE_FLOATS)                // 20736
#define GEMM_SMEM_BYTES  (GEMM_SMEM_FLOATS*4)                 // 82944
#define LSTM_SMEM_FLOATS (32*US_STRIDE + HSTAGES*64*HCH_STRIDE + 64*ZS_STRIDE + 64*8)
#define LSTM_SMEM_BYTES  (LSTM_SMEM_FLOATS*4)                 // 213504

// ---------------- scratch (device globals: allocation-free) ----------------
__device__ float    g_xz[(size_t)TT*BB*G4];     // [T][B][4H] fp32 (256 MB), reused by both layers
__device__ float    g_seq1[(size_t)BB*TT*HH];   // [B][T][H]  layer-1 output, stored tf32-rounded
__device__ float    g_xr[(size_t)BB*TT*DD];     // x pre-rounded to tf32
__device__ float    g_W1r[(size_t)DD*G4];       // W1 pre-rounded
__device__ float    g_W2r[(size_t)HH*G4];       // W2 pre-rounded
__device__ float    g_h1[2*BB*HH];              // double-buffered h, layer 1 (tf32-rounded)
__device__ float    g_h2[2*BB*HH];              // double-buffered h, layer 2 (tf32-rounded)
// barrier state: per-CTA arrive slots (128B stride = private L2 lines) + one release epoch per layer
__device__ unsigned g_flag[2][NCTA * 32];
__device__ unsigned g_epoch[2];

// ---------------- helpers ----------------
__device__ __forceinline__ unsigned f2tf(float f) {
    unsigned u; asm("cvt.rna.tf32.f32 %0, %1;" : "=r"(u) : "f"(f)); return u;
}

__device__ __forceinline__ void mma_tf32(float c[4], const unsigned a[4], unsigned b0, unsigned b1) {
    asm volatile(
        "mma.sync.aligned.m16n8k8.row.col.f32.tf32.tf32.f32 "
        "{%0,%1,%2,%3}, {%4,%5,%6,%7}, {%8,%9}, {%0,%1,%2,%3};\n"
        : "+f"(c[0]), "+f"(c[1]), "+f"(c[2]), "+f"(c[3])
        : "r"(a[0]), "r"(a[1]), "r"(a[2]), "r"(a[3]), "r"(b0), "r"(b1));
}

__device__ __forceinline__ void cp16_ca(void* smem_dst, const float* gsrc) {
    unsigned d = (unsigned)__cvta_generic_to_shared(smem_dst);
    asm volatile("cp.async.ca.shared.global [%0], [%1], 16;\n" :: "r"(d), "l"(gsrc) : "memory");
}
__device__ __forceinline__ void cp16_cg(void* smem_dst, const float* gsrc) {
    unsigned d = (unsigned)__cvta_generic_to_shared(smem_dst);
    asm volatile("cp.async.cg.shared.global [%0], [%1], 16;\n" :: "r"(d), "l"(gsrc) : "memory");
}
__device__ __forceinline__ void cp_commit() { asm volatile("cp.async.commit_group;\n" ::: "memory"); }
__device__ __forceinline__ void cp_wait1() { asm volatile("cp.async.wait_group 1;\n" ::: "memory"); }
__device__ __forceinline__ void cp_wait2() { asm volatile("cp.async.wait_group 2;\n" ::: "memory"); }

__device__ __forceinline__ float sigf(float x) { return 1.f / (1.f + __expf(-x)); }

// ---------------- init: zero h buffers + barrier state each replay ----------------
__global__ void init_zero() {
    int idx = blockIdx.x * blockDim.x + threadIdx.x;
    int stride = gridDim.x * blockDim.x;
    for (int i = idx; i < 2 * BB * HH; i += stride) { g_h1[i] = 0.f; g_h2[i] = 0.f; }
    for (int i = idx; i < NCTA * 32; i += stride) { g_flag[0][i] = 0u; g_flag[1][i] = 0u; }
    if (idx == 0) { g_epoch[0] = 0u; g_epoch[1] = 0u; }
}

// ---------------- pre-round fp32 -> tf32 bits (once per replay) ----------------
__global__ void __launch_bounds__(256)
cvt_round(const float* __restrict__ src, int which, int n4) {
    float* dst = (which == 0) ? g_xr : (which == 1) ? g_W1r : g_W2r;
    int idx = blockIdx.x * blockDim.x + threadIdx.x;
    int stride = gridDim.x * blockDim.x;
    const float4* s4 = (const float4*)src;
    float4* d4 = (float4*)dst;
    for (int i = idx; i < n4; i += stride) {
        float4 v = s4[i];
        v.x = __uint_as_float(f2tf(v.x));
        v.y = __uint_as_float(f2tf(v.y));
        v.z = __uint_as_float(f2tf(v.z));
        v.w = __uint_as_float(f2tf(v.w));
        d4[i] = v;
    }
}

// ---------------- feedforward GEMM: g_xz[t*B+b][0:4096] = A(b,t) @ W + bias ----------------
// asel 0: A = g_xr (layout [B][T][D]); asel 1: A = g_seq1 ([B][T][H]). Inputs pre-rounded to tf32.
__global__ void __launch_bounds__(256)
gemm_xw(int asel, const float* __restrict__ bias, int K, int sAb, int sAt)
{
    extern __shared__ float sm[];
    const float* A = asel ? g_seq1 : g_xr;
    const float* W = asel ? g_W2r : g_W1r;

    const int tid = threadIdx.x;
    const int lane = tid & 31, w = tid >> 5;
    const int wm = w & 3, wn = w >> 2;
    const int bn = blockIdx.x * 64;
    const int bm = blockIdx.y * 128;

    float cf[2][4][4];
#pragma unroll
    for (int i = 0; i < 2; i++)
#pragma unroll
        for (int j = 0; j < 4; j++)
#pragma unroll
            for (int q = 0; q < 4; q++) cf[i][j][q] = 0.f;

    const int KB = K >> 5;

    auto dostage = [&](int slot, int kb) {
        float* As = sm + slot * GEMM_STAGE_FLOATS;
        float* Ws = As + 128 * AS_STRIDE;
        const int k0 = kb * 32;
#pragma unroll
        for (int i = 0; i < 4; i++) {           // A: 128 rows x 8 float4
            int idx = i * 256 + tid;
            int r = idx >> 3, s = idx & 7;
            int m = bm + r;
            const float* src = A + (size_t)(m & 63) * sAb + (size_t)(m >> 6) * sAt + k0 + s * 4;
            cp16_ca(&As[r * AS_STRIDE + s * 4], src);
        }
#pragma unroll
        for (int i = 0; i < 2; i++) {           // W: 32 rows x 16 float4
            int idx = i * 256 + tid;
            int r = idx >> 4, s = idx & 15;
            const float* src = W + (size_t)(k0 + r) * G4 + bn + s * 4;
            cp16_ca(&Ws[r * WS_STRIDE + s * 4], src);
        }
    };

    // 3-stage ring, always-commit: 1 sync per kb
    dostage(0, 0); cp_commit();
    dostage(1, 1); cp_commit();

    const int lr = lane >> 2, lc = lane & 3;

    for (int kb = 0; kb < KB; kb++) {
        cp_wait1();            // chunk kb resident (<=1 newer group pending)
        __syncthreads();       // all warps done with slot (kb-1)%3
        if (kb + 2 < KB) dostage((kb + 2) % 3, kb + 2);
        cp_commit();           // empty-group commit keeps the count uniform
        const float* as = sm + (kb % 3) * GEMM_STAGE_FLOATS;
        const float* ws = as + 128 * AS_STRIDE;
#pragma unroll
        for (int k8 = 0; k8 < 4; k8++) {
            unsigned a[2][4];
#pragma unroll
            for (int mt = 0; mt < 2; mt++) {
                int r0 = wm * 32 + mt * 16 + lr;
                a[mt][0] = __float_as_uint(as[r0 * AS_STRIDE + k8 * 8 + lc]);
                a[mt][1] = __float_as_uint(as[(r0 + 8) * AS_STRIDE + k8 * 8 + lc]);
                a[mt][2] = __float_as_uint(as[r0 * AS_STRIDE + k8 * 8 + lc + 4]);
                a[mt][3] = __float_as_uint(as[(r0 + 8) * AS_STRIDE + k8 * 8 + lc + 4]);
            }
#pragma unroll
            for (int nt = 0; nt < 4; nt++) {
                int c0 = wn * 32 + nt * 8 + lr;
                unsigned b0 = __float_as_uint(ws[(k8 * 8 + lc) * WS_STRIDE + c0]);
                unsigned b1 = __float_as_uint(ws[(k8 * 8 + lc + 4) * WS_STRIDE + c0]);
#pragma unroll
                for (int mt = 0; mt < 2; mt++) mma_tf32(cf[mt][nt], a[mt], b0, b1);
            }
        }
    }

    // epilogue (+bias)
#pragma unroll
    for (int mt = 0; mt < 2; mt++) {
#pragma unroll
        for (int nt = 0; nt < 4; nt++) {
            int gr = bm + wm * 32 + mt * 16 + lr;
            int gc = bn + wn * 32 + nt * 8 + 2 * lc;
            float bv0 = bias[gc], bv1 = bias[gc + 1];
            float2 v;
            v.x = cf[mt][nt][0] + bv0; v.y = cf[mt][nt][1] + bv1;
            *(float2*)&g_xz[(size_t)gr * G4 + gc] = v;
            v.x = cf[mt][nt][2] + bv0; v.y = cf[mt][nt][3] + bv1;
            *(float2*)&g_xz[(size_t)(gr + 8) * G4 + gc] = v;
        }
    }
}

// ---------------- persistent LSTM scan ----------------
__device__ __forceinline__ void lstm_load_chunk(const float* hr, int ch, float* stage, int tid) {
#pragma unroll
    for (int i = 0; i < 4; i++) {   // 64 rows x 16 float4
        int idx = i * 256 + tid;
        int r = idx >> 4, s = idx & 15;
        cp16_cg(stage + r * HCH_STRIDE + s * 4, hr + (size_t)r * HH + ch * HCH + s * 4);
    }
}

__global__ void __launch_bounds__(256)
lstm_scan(const float* __restrict__ U, int layer)
{
    extern __shared__ float sm[];
    float* Us  = sm;                                        // [32][US_STRIDE] tf32
    float* Hst = Us + 32 * US_STRIDE;                       // [4][64][HCH_STRIDE]
    float* Zs  = Hst + HSTAGES * 64 * HCH_STRIDE;           // [64][ZS_STRIDE]
    float* Cs  = Zs + 64 * ZS_STRIDE;                       // [64][8] cell state (fp32)

    float* hbuf = (layer == 0) ? g_h1 : g_h2;
    float* seqo = (layer == 0) ? g_seq1 : nullptr;
    volatile unsigned* flags = g_flag[layer];
    volatile unsigned* epoch = &g_epoch[layer];

    const int tid = threadIdx.x, lane = tid & 31, w = tid >> 5;
    const int mw = w & 3, nw = w >> 2;
    const int u0 = blockIdx.x * UPC;

    // Load U slice: Us[c][k] = tf32(U[k][gate*1024 + u0 + u]), c = gate*8+u
    for (int idx = tid; idx < 32 * HH; idx += 256) {
        int k = idx >> 5, c = idx & 31;
        int gcol = (c >> 3) * HH + u0 + (c & 7);
        Us[c * US_STRIDE + k] = __uint_as_float(f2tf(U[(size_t)k * G4 + gcol]));
    }
    for (int i = tid; i < 64 * 8; i += 256) Cs[i] = 0.f;
    __syncthreads();

    const int lr = lane >> 2, lc = lane & 3;

    // gate-work item ownership: p0 = tid, p1 = tid + 256 (512 items = 64 b x 8 u)
    const int b0_ = tid >> 3,        u0_ = tid & 7;
    const int b1_ = (tid + 256) >> 3, u1_ = (tid + 256) & 7;

    for (int t = 0; t < TT; t++) {
        const float* hr = hbuf + (t & 1) * (BB * HH);
        float* hw = hbuf + ((t + 1) & 1) * (BB * HH);

        // ---- prefetch this step's xz gate rows (independent of h; hidden under mma loop)
        const float* xz = g_xz + (size_t)(t * BB) * G4;
        const float* xp0 = xz + (size_t)b0_ * G4 + u0 + u0_;
        const float* xp1 = xz + (size_t)b1_ * G4 + u0 + u1_;
        float xi0 = __ldg(xp0);            float xi1 = __ldg(xp1);
        float xf0 = __ldg(xp0 + HH);       float xf1 = __ldg(xp1 + HH);
        float xg0 = __ldg(xp0 + 2 * HH);   float xg1 = __ldg(xp1 + 2 * HH);
        float xo0 = __ldg(xp0 + 3 * HH);   float xo1 = __ldg(xp1 + 3 * HH);

        float cf[2][4];
#pragma unroll
        for (int i = 0; i < 2; i++)
#pragma unroll
            for (int j = 0; j < 4; j++) cf[i][j] = 0.f;

        // 4-stage ring over 16 chunks, 1 sync per chunk
        lstm_load_chunk(hr, 0, Hst + 0 * 64 * HCH_STRIDE, tid); cp_commit();
        lstm_load_chunk(hr, 1, Hst + 1 * 64 * HCH_STRIDE, tid); cp_commit();
        lstm_load_chunk(hr, 2, Hst + 2 * 64 * HCH_STRIDE, tid); cp_commit();

        for (int ch = 0; ch < NCH; ch++) {
            cp_wait2();            // chunk ch resident
            __syncthreads();       // everyone finished slot (ch-1)&3
            if (ch + 3 < NCH) lstm_load_chunk(hr, ch + 3, Hst + ((ch + 3) & 3) * 64 * HCH_STRIDE, tid);
            cp_commit();
            const float* hs = Hst + (ch & 3) * 64 * HCH_STRIDE;
#pragma unroll
            for (int k8 = 0; k8 < 8; k8++) {
                unsigned a[4];
                int r0 = mw * 16 + lr;
                a[0] = __float_as_uint(hs[r0 * HCH_STRIDE + k8 * 8 + lc]);
                a[1] = __float_as_uint(hs[(r0 + 8) * HCH_STRIDE + k8 * 8 + lc]);
                a[2] = __float_as_uint(hs[r0 * HCH_STRIDE + k8 * 8 + lc + 4]);
                a[3] = __float_as_uint(hs[(r0 + 8) * HCH_STRIDE + k8 * 8 + lc + 4]);
                int kg = ch * HCH + k8 * 8;
#pragma unroll
                for (int nt = 0; nt < 2; nt++) {
                    int c0 = nw * 16 + nt * 8 + lr;
                    unsigned b0 = __float_as_uint(Us[c0 * US_STRIDE + kg + lc]);
                    unsigned b1 = __float_as_uint(Us[c0 * US_STRIDE + kg + lc + 4]);
                    mma_tf32(cf[nt], a, b0, b1);
                }
            }
        }

        // z fragments -> SMEM
#pragma unroll
        for (int nt = 0; nt < 2; nt++) {
            int zr = mw * 16 + lr;
            int zc = nw * 16 + nt * 8 + 2 * lc;
            *(float2*)&Zs[zr * ZS_STRIDE + zc]       = make_float2(cf[nt][0], cf[nt][1]);
            *(float2*)&Zs[(zr + 8) * ZS_STRIDE + zc] = make_float2(cf[nt][2], cf[nt][3]);
        }
        __syncthreads();

        // gates + state update (fp32); xz already in registers
        {
            // item 0
            float zi = Zs[b0_ * ZS_STRIDE + u0_]      + xi0;
            float zf = Zs[b0_ * ZS_STRIDE + 8 + u0_]  + xf0;
            float zg = Zs[b0_ * ZS_STRIDE + 16 + u0_] + xg0;
            float zo = Zs[b0_ * ZS_STRIDE + 24 + u0_] + xo0;
            float fi = sigf(zi), ff = sigf(zf), fo = sigf(zo);
            float fg = tanhf(zg);
            float cn = ff * Cs[b0_ * 8 + u0_] + fi * fg;
            Cs[b0_ * 8 + u0_] = cn;
            float hn = fo * tanhf(cn);
            float hnr = __uint_as_float(f2tf(hn));
            hw[(size_t)b0_ * HH + u0 + u0_] = hnr;
            if (seqo) seqo[((size_t)b0_ * TT + t) * HH + u0 + u0_] = hnr;
            // item 1
            zi = Zs[b1_ * ZS_STRIDE + u1_]      + xi1;
            zf = Zs[b1_ * ZS_STRIDE + 8 + u1_]  + xf1;
            zg = Zs[b1_ * ZS_STRIDE + 16 + u1_] + xg1;
            zo = Zs[b1_ * ZS_STRIDE + 24 + u1_] + xo1;
            fi = sigf(zi); ff = sigf(zf); fo = sigf(zo);
            fg = tanhf(zg);
            cn = ff * Cs[b1_ * 8 + u1_] + fi * fg;
            Cs[b1_ * 8 + u1_] = cn;
            hn = fo * tanhf(cn);
            hnr = __uint_as_float(f2tf(hn));
            hw[(size_t)b1_ * HH + u0 + u1_] = hnr;
            if (seqo) seqo[((size_t)b1_ * TT + t) * HH + u0 + u1_] = hnr;
        }

        // ---- grid barrier: per-CTA arrive slots + single release epoch ----
        __threadfence();                 // h writes visible GPU-wide
        __syncthreads();                 // whole CTA done writing h
        if (tid == 0) flags[blockIdx.x * 32] = (unsigned)(t + 1);   // private line, no serialization
        if (blockIdx.x == 0) {
            if (tid < NCTA) {            // 128 threads poll 128 distinct lines in parallel
                while (flags[tid * 32] < (unsigned)(t + 1)) { }
            }
            __syncthreads();
            if (tid == 0) *epoch = (unsigned)(t + 1);
        }
        if (tid == 0) {
            while (*epoch < (unsigned)(t + 1)) { __nanosleep(32); }
        }
        __syncthreads();
        __threadfence();
    }
}

// ---------------- final dense: out[b][o] = h2_final[b] . Wd[:,o] + bd[o] ----------------
__global__ void __launch_bounds__(512)
dense_out(const float* __restrict__ Wd, const float* __restrict__ bd, float* __restrict__ out)
{
    __shared__ float hs[HH];
    int b = blockIdx.x;
    const float* h = g_h2; // h_256 lives in stage 0 (T even)
    for (int i = threadIdx.x; i < HH; i += 512) hs[i] = h[(size_t)b * HH + i];
    __syncthreads();
    int o = threadIdx.x;
    float acc = bd[o];
#pragma unroll 8
    for (int k = 0; k < HH; k++) acc += hs[k] * Wd[(size_t)k * 512 + o];
    out[(size_t)b * 512 + o] = acc;
}

// ---------------- launch ----------------
extern "C" void kernel_launch(void* const* d_in, const int* in_sizes, int n_in,
                              void* d_out, int out_size)
{
    (void)in_sizes; (void)n_in; (void)out_size;
    const float* x  = (const float*)d_in[0];
    const float* W1 = (const float*)d_in[1];
    const float* U1 = (const float*)d_in[2];
    const float* b1 = (const float*)d_in[3];
    const float* W2 = (const float*)d_in[4];
    const float* U2 = (const float*)d_in[5];
    const float* b2 = (const float*)d_in[6];
    const float* Wd = (const float*)d_in[7];
    const float* bd = (const float*)d_in[8];
    float* out = (float*)d_out;

    cudaFuncSetAttribute(gemm_xw,  cudaFuncAttributeMaxDynamicSharedMemorySize, GEMM_SMEM_BYTES);
    cudaFuncSetAttribute(lstm_scan, cudaFuncAttributeMaxDynamicSharedMemorySize, LSTM_SMEM_BYTES);

    init_zero<<<128, 256>>>();
    cvt_round<<<1024, 256>>>(x,  0, (BB * TT * DD) / 4);
    cvt_round<<<1024, 256>>>(W1, 1, (DD * G4) / 4);
    cvt_round<<<1024, 256>>>(W2, 2, (HH * G4) / 4);

    dim3 gg(G4 / 64, (BB * TT) / 128);
    // layer 1: xz = x @ W1 + b1   (A row (b,t): x + b*T*D + t*D)
    gemm_xw<<<gg, 256, GEMM_SMEM_BYTES>>>(0, b1, DD, TT * DD, DD);
    lstm_scan<<<NCTA, 256, LSTM_SMEM_BYTES>>>(U1, 0);
    // layer 2: xz = seq1 @ W2 + b2 (A row (b,t): seq1 + b*T*H + t*H)
    gemm_xw<<<gg, 256, GEMM_SMEM_BYTES>>>(1, b2, HH, TT * HH, HH);
    lstm_scan<<<NCTA, 256, LSTM_SMEM_BYTES>>>(U2, 1);

    dense_out<<<BB, 512>>>(Wd, bd, out);
}

// round 7
// speedup vs baseline: 1.1441x; 1.0403x over previous
#include <cuda_runtime.h>
#include <cstdint>
#include <cstddef>

// Problem dims
#define BB 64
#define TT 256
#define DD 512
#define HH 1024
#define G4 4096
#define NCTA 128
#define UPC 8     // units per CTA (32 gate-cols)
// SMEM strides
#define US_STRIDE 1028
#define AS_STRIDE 36
#define WS_STRIDE 72
// LSTM h chunking
#define KCH 64          // k per chunk
#define NCH 16          // chunks per step
#define HCH_STRIDE 68   // smem row stride for a chunk
#define HSTAGES 4
#define SLOT_FLOATS (64*HCH_STRIDE)      // 4352
#define PLANE_FLOATS (64*33)             // 2112 (partial-sum plane)

#define GEMM_STAGE_FLOATS (128*AS_STRIDE + 32*WS_STRIDE)
#define GEMM_SMEM_BYTES  (3*GEMM_STAGE_FLOATS*4)                  // 82944
#define LSTM_SMEM_FLOATS (32*US_STRIDE + HSTAGES*SLOT_FLOATS)     // 50304
#define LSTM_SMEM_BYTES  (LSTM_SMEM_FLOATS*4)                     // 201216

// ---------------- scratch (device globals: allocation-free) ----------------
__device__ float    g_xz[(size_t)TT*BB*G4];     // [T][B][4H] fp32, reused by both layers
__device__ float    g_seq1[(size_t)BB*TT*HH];   // [B][T][H]  layer-1 output (tf32-rounded)
__device__ float    g_xr[(size_t)BB*TT*DD];     // x pre-rounded to tf32
__device__ float    g_W1r[(size_t)DD*G4];
__device__ float    g_W2r[(size_t)HH*G4];
__device__ float    g_h1[2*BB*HH];              // double-buffered h, layer 1 (tf32-rounded)
__device__ float    g_h2[2*BB*HH];
__device__ unsigned g_flag[2][NCTA * 32];
__device__ unsigned g_epoch[2];

// ---------------- helpers ----------------
__device__ __forceinline__ unsigned f2tf(float f) {
    unsigned u; asm("cvt.rna.tf32.f32 %0, %1;" : "=r"(u) : "f"(f)); return u;
}

__device__ __forceinline__ void mma_tf32(float c[4], const unsigned a[4], unsigned b0, unsigned b1) {
    asm volatile(
        "mma.sync.aligned.m16n8k8.row.col.f32.tf32.tf32.f32 "
        "{%0,%1,%2,%3}, {%4,%5,%6,%7}, {%8,%9}, {%0,%1,%2,%3};\n"
        : "+f"(c[0]), "+f"(c[1]), "+f"(c[2]), "+f"(c[3])
        : "r"(a[0]), "r"(a[1]), "r"(a[2]), "r"(a[3]), "r"(b0), "r"(b1));
}

__device__ __forceinline__ void cp16_ca(void* smem_dst, const float* gsrc) {
    unsigned d = (unsigned)__cvta_generic_to_shared(smem_dst);
    asm volatile("cp.async.ca.shared.global [%0], [%1], 16;\n" :: "r"(d), "l"(gsrc) : "memory");
}
__device__ __forceinline__ void cp16_cg(void* smem_dst, const float* gsrc) {
    unsigned d = (unsigned)__cvta_generic_to_shared(smem_dst);
    asm volatile("cp.async.cg.shared.global [%0], [%1], 16;\n" :: "r"(d), "l"(gsrc) : "memory");
}
__device__ __forceinline__ void cp_commit() { asm volatile("cp.async.commit_group;\n" ::: "memory"); }
__device__ __forceinline__ void cp_wait1() { asm volatile("cp.async.wait_group 1;\n" ::: "memory"); }
__device__ __forceinline__ void cp_wait2() { asm volatile("cp.async.wait_group 2;\n" ::: "memory"); }

__device__ __forceinline__ float sigf(float x) { return 1.f / (1.f + __expf(-x)); }

// ---------------- init ----------------
__global__ void init_zero() {
    int idx = blockIdx.x * blockDim.x + threadIdx.x;
    int stride = gridDim.x * blockDim.x;
    for (int i = idx; i < 2 * BB * HH; i += stride) { g_h1[i] = 0.f; g_h2[i] = 0.f; }
    for (int i = idx; i < NCTA * 32; i += stride) { g_flag[0][i] = 0u; g_flag[1][i] = 0u; }
    if (idx == 0) { g_epoch[0] = 0u; g_epoch[1] = 0u; }
}

// ---------------- pre-round fp32 -> tf32 ----------------
__global__ void __launch_bounds__(256)
cvt_round(const float* __restrict__ src, int which, int n4) {
    float* dst = (which == 0) ? g_xr : (which == 1) ? g_W1r : g_W2r;
    int idx = blockIdx.x * blockDim.x + threadIdx.x;
    int stride = gridDim.x * blockDim.x;
    const float4* s4 = (const float4*)src;
    float4* d4 = (float4*)dst;
    for (int i = idx; i < n4; i += stride) {
        float4 v = s4[i];
        v.x = __uint_as_float(f2tf(v.x));
        v.y = __uint_as_float(f2tf(v.y));
        v.z = __uint_as_float(f2tf(v.z));
        v.w = __uint_as_float(f2tf(v.w));
        d4[i] = v;
    }
}

// ---------------- feedforward GEMM (unchanged, passing) ----------------
__global__ void __launch_bounds__(256)
gemm_xw(int asel, const float* __restrict__ bias, int K, int sAb, int sAt)
{
    extern __shared__ float sm[];
    const float* A = asel ? g_seq1 : g_xr;
    const float* W = asel ? g_W2r : g_W1r;

    const int tid = threadIdx.x;
    const int lane = tid & 31, w = tid >> 5;
    const int wm = w & 3, wn = w >> 2;
    const int bn = blockIdx.x * 64;
    const int bm = blockIdx.y * 128;

    float cf[2][4][4];
#pragma unroll
    for (int i = 0; i < 2; i++)
#pragma unroll
        for (int j = 0; j < 4; j++)
#pragma unroll
            for (int q = 0; q < 4; q++) cf[i][j][q] = 0.f;

    const int KB = K >> 5;

    auto dostage = [&](int slot, int kb) {
        float* As = sm + slot * GEMM_STAGE_FLOATS;
        float* Ws = As + 128 * AS_STRIDE;
        const int k0 = kb * 32;
#pragma unroll
        for (int i = 0; i < 4; i++) {
            int idx = i * 256 + tid;
            int r = idx >> 3, s = idx & 7;
            int m = bm + r;
            const float* src = A + (size_t)(m & 63) * sAb + (size_t)(m >> 6) * sAt + k0 + s * 4;
            cp16_ca(&As[r * AS_STRIDE + s * 4], src);
        }
#pragma unroll
        for (int i = 0; i < 2; i++) {
            int idx = i * 256 + tid;
            int r = idx >> 4, s = idx & 15;
            const float* src = W + (size_t)(k0 + r) * G4 + bn + s * 4;
            cp16_ca(&Ws[r * WS_STRIDE + s * 4], src);
        }
    };

    dostage(0, 0); cp_commit();
    dostage(1, 1); cp_commit();

    const int lr = lane >> 2, lc = lane & 3;

    for (int kb = 0; kb < KB; kb++) {
        cp_wait1();
        __syncthreads();
        if (kb + 2 < KB) dostage((kb + 2) % 3, kb + 2);
        cp_commit();
        const float* as = sm + (kb % 3) * GEMM_STAGE_FLOATS;
        const float* ws = as + 128 * AS_STRIDE;
#pragma unroll
        for (int k8 = 0; k8 < 4; k8++) {
            unsigned a[2][4];
#pragma unroll
            for (int mt = 0; mt < 2; mt++) {
                int r0 = wm * 32 + mt * 16 + lr;
                a[mt][0] = __float_as_uint(as[r0 * AS_STRIDE + k8 * 8 + lc]);
                a[mt][1] = __float_as_uint(as[(r0 + 8) * AS_STRIDE + k8 * 8 + lc]);
                a[mt][2] = __float_as_uint(as[r0 * AS_STRIDE + k8 * 8 + lc + 4]);
                a[mt][3] = __float_as_uint(as[(r0 + 8) * AS_STRIDE + k8 * 8 + lc + 4]);
            }
#pragma unroll
            for (int nt = 0; nt < 4; nt++) {
                int c0 = wn * 32 + nt * 8 + lr;
                unsigned b0 = __float_as_uint(ws[(k8 * 8 + lc) * WS_STRIDE + c0]);
                unsigned b1 = __float_as_uint(ws[(k8 * 8 + lc + 4) * WS_STRIDE + c0]);
#pragma unroll
                for (int mt = 0; mt < 2; mt++) mma_tf32(cf[mt][nt], a[mt], b0, b1);
            }
        }
    }

#pragma unroll
    for (int mt = 0; mt < 2; mt++) {
#pragma unroll
        for (int nt = 0; nt < 4; nt++) {
            int gr = bm + wm * 32 + mt * 16 + lr;
            int gc = bn + wn * 32 + nt * 8 + 2 * lc;
            float bv0 = bias[gc], bv1 = bias[gc + 1];
            float2 v;
            v.x = cf[mt][nt][0] + bv0; v.y = cf[mt][nt][1] + bv1;
            *(float2*)&g_xz[(size_t)gr * G4 + gc] = v;
            v.x = cf[mt][nt][2] + bv0; v.y = cf[mt][nt][3] + bv1;
            *(float2*)&g_xz[(size_t)(gr + 8) * G4 + gc] = v;
        }
    }
}

// ---------------- persistent LSTM scan: chunk-local split-K mma tiling ----------------
// Each warp owns k8-slice (wid) of every 64-k chunk, computing a PARTIAL of the full
// 64x32 z tile (zero fragment duplication across warps). Partials reduced in SMEM at
// step end (overlaying the then-free h staging area).
__device__ __forceinline__ void lstm_load_chunk(const float* hr, int ch, float* stage, int tid) {
#pragma unroll
    for (int i = 0; i < 4; i++) {   // 64 rows x 16 float4
        int idx = i * 256 + tid;
        int r = idx >> 4, s = idx & 15;
        cp16_cg(stage + r * HCH_STRIDE + s * 4, hr + (size_t)r * HH + ch * KCH + s * 4);
    }
}

__global__ void __launch_bounds__(256)
lstm_scan(const float* __restrict__ U, int layer)
{
    extern __shared__ float sm[];
    float* Us  = sm;                          // [32][US_STRIDE] tf32 (resident)
    float* Hst = Us + 32 * US_STRIDE;         // [4][64][HCH_STRIDE]; overlaid by partials at step end

    float* hbuf = (layer == 0) ? g_h1 : g_h2;
    float* seqo = (layer == 0) ? g_seq1 : nullptr;
    volatile unsigned* flags = g_flag[layer];
    volatile unsigned* epoch = &g_epoch[layer];

    const int tid = threadIdx.x, lane = tid & 31, wid = tid >> 5;
    const int u0 = blockIdx.x * UPC;
    const int lr = lane >> 2, lc = lane & 3;

    // Load U slice: Us[c][k] = tf32(U[k][gate*1024 + u0 + u]), c = gate*8+u
    for (int idx = tid; idx < 32 * HH; idx += 256) {
        int k = idx >> 5, c = idx & 31;
        int gcol = (c >> 3) * HH + u0 + (c & 7);
        Us[c * US_STRIDE + k] = __uint_as_float(f2tf(U[(size_t)k * G4 + gcol]));
    }
    __syncthreads();

    // gate-work items: p0 = tid, p1 = tid + 256 (512 items = 64 b x 8 u)
    const int b0_ = tid >> 3,         u0_ = tid & 7;
    const int b1_ = (tid + 256) >> 3, u1_ = (tid + 256) & 7;
    float cc0 = 0.f, cc1 = 0.f;   // cell state in registers

    // partial accumulators: full 64x32 tile (4 m-tiles x 4 n8)
    float cf[4][4][4];
#pragma unroll
    for (int mt = 0; mt < 4; mt++)
#pragma unroll
        for (int n8 = 0; n8 < 4; n8++)
#pragma unroll
            for (int q = 0; q < 4; q++) cf[mt][n8][q] = 0.f;

    const int klocal = wid * 8;   // this warp's k8 slice within every chunk

    for (int t = 0; t < TT; t++) {
        const float* hr = hbuf + (t & 1) * (BB * HH);
        float* hw = hbuf + ((t + 1) & 1) * (BB * HH);

        // prefetch xz gate rows (independent of h)
        const float* xz = g_xz + (size_t)(t * BB) * G4;
        const float* xp0 = xz + (size_t)b0_ * G4 + u0 + u0_;
        const float* xp1 = xz + (size_t)b1_ * G4 + u0 + u1_;
        float xi0 = __ldg(xp0);            float xi1 = __ldg(xp1);
        float xf0 = __ldg(xp0 + HH);       float xf1 = __ldg(xp1 + HH);
        float xg0 = __ldg(xp0 + 2 * HH);   float xg1 = __ldg(xp1 + 2 * HH);
        float xo0 = __ldg(xp0 + 3 * HH);   float xo1 = __ldg(xp1 + 3 * HH);

        // 4-stage ring over 16 chunks
        lstm_load_chunk(hr, 0, Hst + 0 * SLOT_FLOATS, tid); cp_commit();
        lstm_load_chunk(hr, 1, Hst + 1 * SLOT_FLOATS, tid); cp_commit();
        lstm_load_chunk(hr, 2, Hst + 2 * SLOT_FLOATS, tid); cp_commit();

        for (int ch = 0; ch < NCH; ch++) {
            cp_wait2();            // chunk ch resident
            __syncthreads();       // all warps finished slot (ch-1)&3
            if (ch + 3 < NCH) lstm_load_chunk(hr, ch + 3, Hst + ((ch + 3) & 3) * SLOT_FLOATS, tid);
            cp_commit();
            const float* hs = Hst + (ch & 3) * SLOT_FLOATS;

            // this warp's A fragments: all 4 m-tiles of its k8 slice (each byte read ONCE chip-wide)
            unsigned a[4][4];
#pragma unroll
            for (int mt = 0; mt < 4; mt++) {
                int r0 = mt * 16 + lr;
                a[mt][0] = __float_as_uint(hs[r0 * HCH_STRIDE + klocal + lc]);
                a[mt][1] = __float_as_uint(hs[(r0 + 8) * HCH_STRIDE + klocal + lc]);
                a[mt][2] = __float_as_uint(hs[r0 * HCH_STRIDE + klocal + lc + 4]);
                a[mt][3] = __float_as_uint(hs[(r0 + 8) * HCH_STRIDE + klocal + lc + 4]);
            }
            int kg = ch * KCH + klocal;
#pragma unroll
            for (int n8 = 0; n8 < 4; n8++) {
                int c0 = n8 * 8 + lr;
                unsigned b0 = __float_as_uint(Us[c0 * US_STRIDE + kg + lc]);
                unsigned b1 = __float_as_uint(Us[c0 * US_STRIDE + kg + lc + 4]);
#pragma unroll
                for (int mt = 0; mt < 4; mt++) mma_tf32(cf[mt][n8], a[mt], b0, b1);
            }
        }

        // all warps done reading slot 3 before partial planes overlay the staging area
        __syncthreads();

        // store this warp's partial plane (stride-33 rows), reset accumulators
        {
            float* pl = Hst + wid * PLANE_FLOATS;
#pragma unroll
            for (int mt = 0; mt < 4; mt++)
#pragma unroll
                for (int n8 = 0; n8 < 4; n8++) {
                    int zr = mt * 16 + lr, zc = n8 * 8 + 2 * lc;
                    pl[zr * 33 + zc]           = cf[mt][n8][0];
                    pl[zr * 33 + zc + 1]       = cf[mt][n8][1];
                    pl[(zr + 8) * 33 + zc]     = cf[mt][n8][2];
                    pl[(zr + 8) * 33 + zc + 1] = cf[mt][n8][3];
                    cf[mt][n8][0] = 0.f; cf[mt][n8][1] = 0.f;
                    cf[mt][n8][2] = 0.f; cf[mt][n8][3] = 0.f;
                }
        }
        __syncthreads();

        // reduce 8 planes + gate math (2 items per thread)
        {
            float s0 = 0.f, s1 = 0.f, s2 = 0.f, s3 = 0.f;
            float r0 = 0.f, r1 = 0.f, r2 = 0.f, r3 = 0.f;
#pragma unroll
            for (int pw = 0; pw < 8; pw++) {
                const float* pa = Hst + pw * PLANE_FLOATS + b0_ * 33;
                const float* pb = Hst + pw * PLANE_FLOATS + b1_ * 33;
                s0 += pa[u0_];      s1 += pa[8 + u0_];
                s2 += pa[16 + u0_]; s3 += pa[24 + u0_];
                r0 += pb[u1_];      r1 += pb[8 + u1_];
                r2 += pb[16 + u1_]; r3 += pb[24 + u1_];
            }
            // item 0
            float zi = s0 + xi0, zf = s1 + xf0, zg = s2 + xg0, zo = s3 + xo0;
            float fi = sigf(zi), ff = sigf(zf), fo = sigf(zo);
            float fg = tanhf(zg);
            float cn = ff * cc0 + fi * fg;
            cc0 = cn;
            float hnr = __uint_as_float(f2tf(fo * tanhf(cn)));
            hw[(size_t)b0_ * HH + u0 + u0_] = hnr;
            if (seqo) seqo[((size_t)b0_ * TT + t) * HH + u0 + u0_] = hnr;
            // item 1
            zi = r0 + xi1; zf = r1 + xf1; zg = r2 + xg1; zo = r3 + xo1;
            fi = sigf(zi); ff = sigf(zf); fo = sigf(zo);
            fg = tanhf(zg);
            cn = ff * cc1 + fi * fg;
            cc1 = cn;
            hnr = __uint_as_float(f2tf(fo * tanhf(cn)));
            hw[(size_t)b1_ * HH + u0 + u1_] = hnr;
            if (seqo) seqo[((size_t)b1_ * TT + t) * HH + u0 + u1_] = hnr;
        }

        // grid barrier: per-CTA arrive slots + single release epoch (proven R4/R5 pattern)
        __threadfence();
        __syncthreads();
        if (tid == 0) flags[blockIdx.x * 32] = (unsigned)(t + 1);
        if (blockIdx.x == 0) {
            if (tid < NCTA) {
                while (flags[tid * 32] < (unsigned)(t + 1)) { }
            }
            __syncthreads();
            if (tid == 0) *epoch = (unsigned)(t + 1);
        }
        if (tid == 0) {
            while (*epoch < (unsigned)(t + 1)) { __nanosleep(32); }
        }
        __syncthreads();
        __threadfence();
    }
}

// ---------------- final dense ----------------
__global__ void __launch_bounds__(512)
dense_out(const float* __restrict__ Wd, const float* __restrict__ bd, float* __restrict__ out)
{
    __shared__ float hs[HH];
    int b = blockIdx.x;
    const float* h = g_h2; // h_256 lives in stage 0 (T even)
    for (int i = threadIdx.x; i < HH; i += 512) hs[i] = h[(size_t)b * HH + i];
    __syncthreads();
    int o = threadIdx.x;
    float acc = bd[o];
#pragma unroll 8
    for (int k = 0; k < HH; k++) acc += hs[k] * Wd[(size_t)k * 512 + o];
    out[(size_t)b * 512 + o] = acc;
}

// ---------------- launch ----------------
extern "C" void kernel_launch(void* const* d_in, const int* in_sizes, int n_in,
                              void* d_out, int out_size)
{
    (void)in_sizes; (void)n_in; (void)out_size;
    const float* x  = (const float*)d_in[0];
    const float* W1 = (const float*)d_in[1];
    const float* U1 = (const float*)d_in[2];
    const float* b1 = (const float*)d_in[3];
    const float* W2 = (const float*)d_in[4];
    const float* U2 = (const float*)d_in[5];
    const float* b2 = (const float*)d_in[6];
    const float* Wd = (const float*)d_in[7];
    const float* bd = (const float*)d_in[8];
    float* out = (float*)d_out;

    cudaFuncSetAttribute(gemm_xw,  cudaFuncAttributeMaxDynamicSharedMemorySize, GEMM_SMEM_BYTES);
    cudaFuncSetAttribute(lstm_scan, cudaFuncAttributeMaxDynamicSharedMemorySize, LSTM_SMEM_BYTES);

    init_zero<<<128, 256>>>();
    cvt_round<<<1024, 256>>>(x,  0, (BB * TT * DD) / 4);
    cvt_round<<<1024, 256>>>(W1, 1, (DD * G4) / 4);
    cvt_round<<<1024, 256>>>(W2, 2, (HH * G4) / 4);

    dim3 gg(G4 / 64, (BB * TT) / 128);
    gemm_xw<<<gg, 256, GEMM_SMEM_BYTES>>>(0, b1, DD, TT * DD, DD);
    lstm_scan<<<NCTA, 256, LSTM_SMEM_BYTES>>>(U1, 0);
    gemm_xw<<<gg, 256, GEMM_SMEM_BYTES>>>(1, b2, HH, TT * HH, HH);
    lstm_scan<<<NCTA, 256, LSTM_SMEM_BYTES>>>(U2, 1);

    dense_out<<<BB, 512>>>(Wd, bd, out);
}

// round 8
// speedup vs baseline: 1.1674x; 1.0204x over previous
#include <cuda_runtime.h>
#include <cstdint>
#include <cstddef>

// Problem dims
#define BB 64
#define TT 256
#define DD 512
#define HH 1024
#define G4 4096
#define NCTA 128
#define UPC 8     // units per CTA (32 gate-cols)
// time chunking for the kernel-level pipeline
#define NTC 8
#define TPC 32
// SMEM strides
#define US_STRIDE 1028
#define AS_STRIDE 36
#define WS_STRIDE 72
// LSTM h chunking
#define KCH 64
#define NCH 16
#define HCH_STRIDE 68
#define HSTAGES 4
#define SLOT_FLOATS (64*HCH_STRIDE)
#define PLANE_FLOATS (64*33)

#define GEMM_STAGE_FLOATS (128*AS_STRIDE + 32*WS_STRIDE)
#define GEMM_SMEM_BYTES  (3*GEMM_STAGE_FLOATS*4)                  // 82944
#define LSTM_SMEM_FLOATS (32*US_STRIDE + HSTAGES*SLOT_FLOATS)
#define LSTM_SMEM_BYTES  (LSTM_SMEM_FLOATS*4)                     // 201216

// ---------------- scratch ----------------
__device__ float    g_xz[(size_t)TT*BB*G4];
__device__ float    g_seq1[(size_t)BB*TT*HH];
__device__ float    g_xr[(size_t)BB*TT*DD];
__device__ float    g_W1r[(size_t)DD*G4];
__device__ float    g_W2r[(size_t)HH*G4];
__device__ float    g_h1[2*BB*HH];
__device__ float    g_h2[2*BB*HH];
__device__ float    g_c1[BB*HH];     // cell state, persists across chunk launches
__device__ float    g_c2[BB*HH];
__device__ unsigned g_flag[2][NCTA * 32];
__device__ unsigned g_epoch[2];

// ---------------- helpers ----------------
__device__ __forceinline__ unsigned f2tf(float f) {
    unsigned u; asm("cvt.rna.tf32.f32 %0, %1;" : "=r"(u) : "f"(f)); return u;
}
__device__ __forceinline__ void mma_tf32(float c[4], const unsigned a[4], unsigned b0, unsigned b1) {
    asm volatile(
        "mma.sync.aligned.m16n8k8.row.col.f32.tf32.tf32.f32 "
        "{%0,%1,%2,%3}, {%4,%5,%6,%7}, {%8,%9}, {%0,%1,%2,%3};\n"
        : "+f"(c[0]), "+f"(c[1]), "+f"(c[2]), "+f"(c[3])
        : "r"(a[0]), "r"(a[1]), "r"(a[2]), "r"(a[3]), "r"(b0), "r"(b1));
}
__device__ __forceinline__ void cp16_ca(void* smem_dst, const float* gsrc) {
    unsigned d = (unsigned)__cvta_generic_to_shared(smem_dst);
    asm volatile("cp.async.ca.shared.global [%0], [%1], 16;\n" :: "r"(d), "l"(gsrc) : "memory");
}
__device__ __forceinline__ void cp16_cg(void* smem_dst, const float* gsrc) {
    unsigned d = (unsigned)__cvta_generic_to_shared(smem_dst);
    asm volatile("cp.async.cg.shared.global [%0], [%1], 16;\n" :: "r"(d), "l"(gsrc) : "memory");
}
__device__ __forceinline__ void cp_commit() { asm volatile("cp.async.commit_group;\n" ::: "memory"); }
__device__ __forceinline__ void cp_wait1() { asm volatile("cp.async.wait_group 1;\n" ::: "memory"); }
__device__ __forceinline__ void cp_wait2() { asm volatile("cp.async.wait_group 2;\n" ::: "memory"); }
__device__ __forceinline__ float sigf(float x) { return 1.f / (1.f + __expf(-x)); }

// ---------------- init ----------------
__global__ void init_zero() {
    int idx = blockIdx.x * blockDim.x + threadIdx.x;
    int stride = gridDim.x * blockDim.x;
    for (int i = idx; i < 2 * BB * HH; i += stride) { g_h1[i] = 0.f; g_h2[i] = 0.f; }
    for (int i = idx; i < BB * HH; i += stride) { g_c1[i] = 0.f; g_c2[i] = 0.f; }
    for (int i = idx; i < NCTA * 32; i += stride) { g_flag[0][i] = 0u; g_flag[1][i] = 0u; }
    if (idx == 0) { g_epoch[0] = 0u; g_epoch[1] = 0u; }
}

// ---------------- pre-round fp32 -> tf32 ----------------
__global__ void __launch_bounds__(256)
cvt_round(const float* __restrict__ src, int which, int n4) {
    float* dst = (which == 0) ? g_xr : (which == 1) ? g_W1r : g_W2r;
    int idx = blockIdx.x * blockDim.x + threadIdx.x;
    int stride = gridDim.x * blockDim.x;
    const float4* s4 = (const float4*)src;
    float4* d4 = (float4*)dst;
    for (int i = idx; i < n4; i += stride) {
        float4 v = s4[i];
        v.x = __uint_as_float(f2tf(v.x));
        v.y = __uint_as_float(f2tf(v.y));
        v.z = __uint_as_float(f2tf(v.z));
        v.w = __uint_as_float(f2tf(v.w));
        d4[i] = v;
    }
}

// ---------------- feedforward GEMM (time-chunked: rows [m0, m0+2048)) ----------------
__global__ void __launch_bounds__(256)
gemm_xw(int asel, const float* __restrict__ bias, int K, int sAb, int sAt, int m0)
{
    extern __shared__ float sm[];
    const float* A = asel ? g_seq1 : g_xr;
    const float* W = asel ? g_W2r : g_W1r;

    const int tid = threadIdx.x;
    const int lane = tid & 31, w = tid >> 5;
    const int wm = w & 3, wn = w >> 2;
    const int bn = blockIdx.x * 64;
    const int bm = m0 + blockIdx.y * 128;

    float cf[2][4][4];
#pragma unroll
    for (int i = 0; i < 2; i++)
#pragma unroll
        for (int j = 0; j < 4; j++)
#pragma unroll
            for (int q = 0; q < 4; q++) cf[i][j][q] = 0.f;

    const int KB = K >> 5;

    auto dostage = [&](int slot, int kb) {
        float* As = sm + slot * GEMM_STAGE_FLOATS;
        float* Ws = As + 128 * AS_STRIDE;
        const int k0 = kb * 32;
#pragma unroll
        for (int i = 0; i < 4; i++) {
            int idx = i * 256 + tid;
            int r = idx >> 3, s = idx & 7;
            int m = bm + r;
            const float* src = A + (size_t)(m & 63) * sAb + (size_t)(m >> 6) * sAt + k0 + s * 4;
            cp16_ca(&As[r * AS_STRIDE + s * 4], src);
        }
#pragma unroll
        for (int i = 0; i < 2; i++) {
            int idx = i * 256 + tid;
            int r = idx >> 4, s = idx & 15;
            const float* src = W + (size_t)(k0 + r) * G4 + bn + s * 4;
            cp16_ca(&Ws[r * WS_STRIDE + s * 4], src);
        }
    };

    dostage(0, 0); cp_commit();
    dostage(1, 1); cp_commit();

    const int lr = lane >> 2, lc = lane & 3;

    for (int kb = 0; kb < KB; kb++) {
        cp_wait1();
        __syncthreads();
        if (kb + 2 < KB) dostage((kb + 2) % 3, kb + 2);
        cp_commit();
        const float* as = sm + (kb % 3) * GEMM_STAGE_FLOATS;
        const float* ws = as + 128 * AS_STRIDE;
#pragma unroll
        for (int k8 = 0; k8 < 4; k8++) {
            unsigned a[2][4];
#pragma unroll
            for (int mt = 0; mt < 2; mt++) {
                int r0 = wm * 32 + mt * 16 + lr;
                a[mt][0] = __float_as_uint(as[r0 * AS_STRIDE + k8 * 8 + lc]);
                a[mt][1] = __float_as_uint(as[(r0 + 8) * AS_STRIDE + k8 * 8 + lc]);
                a[mt][2] = __float_as_uint(as[r0 * AS_STRIDE + k8 * 8 + lc + 4]);
                a[mt][3] = __float_as_uint(as[(r0 + 8) * AS_STRIDE + k8 * 8 + lc + 4]);
            }
#pragma unroll
            for (int nt = 0; nt < 4; nt++) {
                int c0 = wn * 32 + nt * 8 + lr;
                unsigned b0 = __float_as_uint(ws[(k8 * 8 + lc) * WS_STRIDE + c0]);
                unsigned b1 = __float_as_uint(ws[(k8 * 8 + lc + 4) * WS_STRIDE + c0]);
#pragma unroll
                for (int mt = 0; mt < 2; mt++) mma_tf32(cf[mt][nt], a[mt], b0, b1);
            }
        }
    }

#pragma unroll
    for (int mt = 0; mt < 2; mt++) {
#pragma unroll
        for (int nt = 0; nt < 4; nt++) {
            int gr = bm + wm * 32 + mt * 16 + lr;
            int gc = bn + wn * 32 + nt * 8 + 2 * lc;
            float bv0 = bias[gc], bv1 = bias[gc + 1];
            float2 v;
            v.x = cf[mt][nt][0] + bv0; v.y = cf[mt][nt][1] + bv1;
            *(float2*)&g_xz[(size_t)gr * G4 + gc] = v;
            v.x = cf[mt][nt][2] + bv0; v.y = cf[mt][nt][3] + bv1;
            *(float2*)&g_xz[(size_t)(gr + 8) * G4 + gc] = v;
        }
    }
}

// ---------------- persistent LSTM scan (split-K tiling), time-chunked ----------------
__device__ __forceinline__ void lstm_load_chunk(const float* hr, int ch, float* stage, int tid) {
#pragma unroll
    for (int i = 0; i < 4; i++) {
        int idx = i * 256 + tid;
        int r = idx >> 4, s = idx & 15;
        cp16_cg(stage + r * HCH_STRIDE + s * 4, hr + (size_t)r * HH + ch * KCH + s * 4);
    }
}

__global__ void __launch_bounds__(256)
lstm_scan(const float* __restrict__ U, int layer, int t0)
{
    extern __shared__ float sm[];
    float* Us  = sm;
    float* Hst = Us + 32 * US_STRIDE;

    float* hbuf = (layer == 0) ? g_h1 : g_h2;
    float* cbuf = (layer == 0) ? g_c1 : g_c2;
    float* seqo = (layer == 0) ? g_seq1 : nullptr;
    volatile unsigned* flags = g_flag[layer];
    volatile unsigned* epoch = &g_epoch[layer];

    const int tid = threadIdx.x, lane = tid & 31, wid = tid >> 5;
    const int u0 = blockIdx.x * UPC;
    const int lr = lane >> 2, lc = lane & 3;

    for (int idx = tid; idx < 32 * HH; idx += 256) {
        int k = idx >> 5, c = idx & 31;
        int gcol = (c >> 3) * HH + u0 + (c & 7);
        Us[c * US_STRIDE + k] = __uint_as_float(f2tf(U[(size_t)k * G4 + gcol]));
    }
    __syncthreads();

    const int b0_ = tid >> 3,         u0_ = tid & 7;
    const int b1_ = (tid + 256) >> 3, u1_ = (tid + 256) & 7;
    float cc0 = cbuf[(size_t)b0_ * HH + u0 + u0_];
    float cc1 = cbuf[(size_t)b1_ * HH + u0 + u1_];

    float cf[4][4][4];
#pragma unroll
    for (int mt = 0; mt < 4; mt++)
#pragma unroll
        for (int n8 = 0; n8 < 4; n8++)
#pragma unroll
            for (int q = 0; q < 4; q++) cf[mt][n8][q] = 0.f;

    const int klocal = wid * 8;

    for (int t = t0; t < t0 + TPC; t++) {
        const float* hr = hbuf + (t & 1) * (BB * HH);
        float* hw = hbuf + ((t + 1) & 1) * (BB * HH);

        const float* xz = g_xz + (size_t)(t * BB) * G4;
        const float* xp0 = xz + (size_t)b0_ * G4 + u0 + u0_;
        const float* xp1 = xz + (size_t)b1_ * G4 + u0 + u1_;
        float xi0 = __ldg(xp0);            float xi1 = __ldg(xp1);
        float xf0 = __ldg(xp0 + HH);       float xf1 = __ldg(xp1 + HH);
        float xg0 = __ldg(xp0 + 2 * HH);   float xg1 = __ldg(xp1 + 2 * HH);
        float xo0 = __ldg(xp0 + 3 * HH);   float xo1 = __ldg(xp1 + 3 * HH);

        lstm_load_chunk(hr, 0, Hst + 0 * SLOT_FLOATS, tid); cp_commit();
        lstm_load_chunk(hr, 1, Hst + 1 * SLOT_FLOATS, tid); cp_commit();
        lstm_load_chunk(hr, 2, Hst + 2 * SLOT_FLOATS, tid); cp_commit();

        for (int ch = 0; ch < NCH; ch++) {
            cp_wait2();
            __syncthreads();
            if (ch + 3 < NCH) lstm_load_chunk(hr, ch + 3, Hst + ((ch + 3) & 3) * SLOT_FLOATS, tid);
            cp_commit();
            const float* hs = Hst + (ch & 3) * SLOT_FLOATS;

            unsigned a[4][4];
#pragma unroll
            for (int mt = 0; mt < 4; mt++) {
                int r0 = mt * 16 + lr;
                a[mt][0] = __float_as_uint(hs[r0 * HCH_STRIDE + klocal + lc]);
                a[mt][1] = __float_as_uint(hs[(r0 + 8) * HCH_STRIDE + klocal + lc]);
                a[mt][2] = __float_as_uint(hs[r0 * HCH_STRIDE + klocal + lc + 4]);
                a[mt][3] = __float_as_uint(hs[(r0 + 8) * HCH_STRIDE + klocal + lc + 4]);
            }
            int kg = ch * KCH + klocal;
#pragma unroll
            for (int n8 = 0; n8 < 4; n8++) {
                int c0 = n8 * 8 + lr;
                unsigned b0 = __float_as_uint(Us[c0 * US_STRIDE + kg + lc]);
                unsigned b1 = __float_as_uint(Us[c0 * US_STRIDE + kg + lc + 4]);
#pragma unroll
                for (int mt = 0; mt < 4; mt++) mma_tf32(cf[mt][n8], a[mt], b0, b1);
            }
        }

        __syncthreads();

        {
            float* pl = Hst + wid * PLANE_FLOATS;
#pragma unroll
            for (int mt = 0; mt < 4; mt++)
#pragma unroll
                for (int n8 = 0; n8 < 4; n8++) {
                    int zr = mt * 16 + lr, zc = n8 * 8 + 2 * lc;
                    pl[zr * 33 + zc]           = cf[mt][n8][0];
                    pl[zr * 33 + zc + 1]       = cf[mt][n8][1];
                    pl[(zr + 8) * 33 + zc]     = cf[mt][n8][2];
                    pl[(zr + 8) * 33 + zc + 1] = cf[mt][n8][3];
                    cf[mt][n8][0] = 0.f; cf[mt][n8][1] = 0.f;
                    cf[mt][n8][2] = 0.f; cf[mt][n8][3] = 0.f;
                }
        }
        __syncthreads();

        {
            float s0 = 0.f, s1 = 0.f, s2 = 0.f, s3 = 0.f;
            float r0 = 0.f, r1 = 0.f, r2 = 0.f, r3 = 0.f;
#pragma unroll
            for (int pw = 0; pw < 8; pw++) {
                const float* pa = Hst + pw * PLANE_FLOATS + b0_ * 33;
                const float* pb = Hst + pw * PLANE_FLOATS + b1_ * 33;
                s0 += pa[u0_];      s1 += pa[8 + u0_];
                s2 += pa[16 + u0_]; s3 += pa[24 + u0_];
                r0 += pb[u1_];      r1 += pb[8 + u1_];
                r2 += pb[16 + u1_]; r3 += pb[24 + u1_];
            }
            float zi = s0 + xi0, zf = s1 + xf0, zg = s2 + xg0, zo = s3 + xo0;
            float fi = sigf(zi), ff = sigf(zf), fo = sigf(zo);
            float fg = tanhf(zg);
            float cn = ff * cc0 + fi * fg;
            cc0 = cn;
            float hnr = __uint_as_float(f2tf(fo * tanhf(cn)));
            hw[(size_t)b0_ * HH + u0 + u0_] = hnr;
            if (seqo) seqo[((size_t)b0_ * TT + t) * HH + u0 + u0_] = hnr;
            zi = r0 + xi1; zf = r1 + xf1; zg = r2 + xg1; zo = r3 + xo1;
            fi = sigf(zi); ff = sigf(zf); fo = sigf(zo);
            fg = tanhf(zg);
            cn = ff * cc1 + fi * fg;
            cc1 = cn;
            hnr = __uint_as_float(f2tf(fo * tanhf(cn)));
            hw[(size_t)b1_ * HH + u0 + u1_] = hnr;
            if (seqo) seqo[((size_t)b1_ * TT + t) * HH + u0 + u1_] = hnr;
        }

        __threadfence();
        __syncthreads();
        if (tid == 0) flags[blockIdx.x * 32] = (unsigned)(t + 1);
        if (blockIdx.x == 0) {
            if (tid < NCTA) {
                while (flags[tid * 32] < (unsigned)(t + 1)) { }
            }
            __syncthreads();
            if (tid == 0) *epoch = (unsigned)(t + 1);
        }
        if (tid == 0) {
            while (*epoch < (unsigned)(t + 1)) { __nanosleep(32); }
        }
        __syncthreads();
        __threadfence();
    }

    cbuf[(size_t)b0_ * HH + u0 + u0_] = cc0;
    cbuf[(size_t)b1_ * HH + u0 + u1_] = cc1;
}

// ---------------- final dense ----------------
__global__ void __launch_bounds__(512)
dense_out(const float* __restrict__ Wd, const float* __restrict__ bd, float* __restrict__ out)
{
    __shared__ float hs[HH];
    int b = blockIdx.x;
    const float* h = g_h2; // h_256 in stage 0 (T even)
    for (int i = threadIdx.x; i < HH; i += 512) hs[i] = h[(size_t)b * HH + i];
    __syncthreads();
    int o = threadIdx.x;
    float acc = bd[o];
#pragma unroll 8
    for (int k = 0; k < HH; k++) acc += hs[k] * Wd[(size_t)k * 512 + o];
    out[(size_t)b * 512 + o] = acc;
}

// ---------------- launch: 3-stream chunked pipeline (graph fork/join via events) ----------------
extern "C" void kernel_launch(void* const* d_in, const int* in_sizes, int n_in,
                              void* d_out, int out_size)
{
    (void)in_sizes; (void)n_in; (void)out_size;
    const float* x  = (const float*)d_in[0];
    const float* W1 = (const float*)d_in[1];
    const float* U1 = (const float*)d_in[2];
    const float* b1 = (const float*)d_in[3];
    const float* W2 = (const float*)d_in[4];
    const float* U2 = (const float*)d_in[5];
    const float* b2 = (const float*)d_in[6];
    const float* Wd = (const float*)d_in[7];
    const float* bd = (const float*)d_in[8];
    float* out = (float*)d_out;

    // streams/events created once (outside any capture); reused every call — same DAG each call
    static cudaStream_t s1 = nullptr, s2 = nullptr;
    static cudaEvent_t evF, evG1[NTC], evL1[NTC], evG2[NTC], evJ1, evJ2;
    if (!s1) {
        cudaStreamCreateWithFlags(&s1, cudaStreamNonBlocking);
        cudaStreamCreateWithFlags(&s2, cudaStreamNonBlocking);
        cudaEventCreateWithFlags(&evF, cudaEventDisableTiming);
        cudaEventCreateWithFlags(&evJ1, cudaEventDisableTiming);
        cudaEventCreateWithFlags(&evJ2, cudaEventDisableTiming);
        for (int k = 0; k < NTC; k++) {
            cudaEventCreateWithFlags(&evG1[k], cudaEventDisableTiming);
            cudaEventCreateWithFlags(&evL1[k], cudaEventDisableTiming);
            cudaEventCreateWithFlags(&evG2[k], cudaEventDisableTiming);
        }
        cudaFuncSetAttribute(gemm_xw,  cudaFuncAttributeMaxDynamicSharedMemorySize, GEMM_SMEM_BYTES);
        cudaFuncSetAttribute(lstm_scan, cudaFuncAttributeMaxDynamicSharedMemorySize, LSTM_SMEM_BYTES);
    }

    // prologue on the main (capturing) stream
    init_zero<<<128, 256>>>();
    cvt_round<<<1024, 256>>>(x,  0, (BB * TT * DD) / 4);
    cvt_round<<<1024, 256>>>(W1, 1, (DD * G4) / 4);
    cvt_round<<<1024, 256>>>(W2, 2, (HH * G4) / 4);

    // fork side streams from main stream
    cudaEventRecord(evF, 0);
    cudaStreamWaitEvent(s1, evF, 0);
    cudaStreamWaitEvent(s2, evF, 0);

    dim3 gg(G4 / 64, (BB * TT / TPC / 64 / NTC) * (TPC * 64) / 128);  // = (64, 16)
    dim3 ggc(G4 / 64, (TPC * 64) / 128);

    // all gemm1 chunks on s1 (serial on s1; each signals its event)
    for (int k = 0; k < NTC; k++) {
        gemm_xw<<<ggc, 256, GEMM_SMEM_BYTES, s1>>>(0, b1, DD, TT * DD, DD, k * TPC * 64);
        cudaEventRecord(evG1[k], s1);
    }

    // pipeline: lstm1 (main stream) / gemm2 (s1) / lstm2 (s2)
    for (int k = 0; k < NTC; k++) {
        cudaStreamWaitEvent(0, evG1[k], 0);
        lstm_scan<<<NCTA, 256, LSTM_SMEM_BYTES>>>(U1, 0, k * TPC);
        cudaEventRecord(evL1[k], 0);

        cudaStreamWaitEvent(s1, evL1[k], 0);
        gemm_xw<<<ggc, 256, GEMM_SMEM_BYTES, s1>>>(1, b2, HH, TT * HH, HH, k * TPC * 64);
        cudaEventRecord(evG2[k], s1);

        cudaStreamWaitEvent(s2, evG2[k], 0);
        lstm_scan<<<NCTA, 256, LSTM_SMEM_BYTES, s2>>>(U2, 1, k * TPC);
    }

    dense_out<<<BB, 512, 0, s2>>>(Wd, bd, out);

    // join both side streams back into the main stream
    cudaEventRecord(evJ1, s1);
    cudaEventRecord(evJ2, s2);
    cudaStreamWaitEvent(0, evJ1, 0);
    cudaStreamWaitEvent(0, evJ2, 0);
}